// round 1
// baseline (speedup 1.0000x reference)
#include <cuda_runtime.h>
#include <cuda_bf16.h>
#include <math.h>

// Problem constants (fixed shapes)
#define NNODES 50000
#define NEDGES 800000
#define FIN    64
#define HID    64

// ---------------- scratch (device globals; no allocation allowed) ----------------
__device__ float g_seg[NNODES * 12];    // segment_sum(trans, row)
__device__ float g_agg[NNODES * 64];    // segment_sum(edge_feat, row)
__device__ float g_oth[NNODES * 64];    // segment_sum(edge_feat, col)
__device__ float g_cnt_row[NNODES];
__device__ float g_cnt_col[NNODES];

__global__ void zero_scratch(int n) {
    int tid = blockIdx.x * blockDim.x + threadIdx.x;
    int stride = gridDim.x * blockDim.x;
    for (int i = tid; i < n * 12; i += stride) g_seg[i] = 0.f;
    for (int i = tid; i < n * 64; i += stride) g_agg[i] = 0.f;
    for (int i = tid; i < n * 64; i += stride) g_oth[i] = 0.f;
    for (int i = tid; i < n; i += stride) { g_cnt_row[i] = 0.f; g_cnt_col[i] = 0.f; }
}

__device__ __forceinline__ void blk_copy(float* dst, const float* src, int n) {
    for (int i = threadIdx.x; i < n; i += blockDim.x) dst[i] = src[i];
}

// ---------------- edge kernel: warp per edge ----------------
// smem layout (floats):
//   We1s  [144*64] = 9216
//   We2s  [64*64]  = 4096
//   Wc1s  [64*64]  = 4096
//   Wc2s  [64]
//   be1s  [64], be2s [64], bc1s [64]
//   per-warp: cd[16], ein[144], hid[64]  (stride 224)
#define EDGE_SMEM_FLOATS (9216 + 4096 + 4096 + 64 + 64 + 64 + 64 + 8 * 224)

__global__ __launch_bounds__(256, 2)
void edge_kernel(const float* __restrict__ h, const float* __restrict__ Z,
                 const int* __restrict__ row, const int* __restrict__ col,
                 const float* __restrict__ We1, const float* __restrict__ be1,
                 const float* __restrict__ We2, const float* __restrict__ be2,
                 const float* __restrict__ Wc1, const float* __restrict__ bc1,
                 const float* __restrict__ Wc2,
                 int E)
{
    extern __shared__ float sm[];
    float* We1s = sm;                    // 9216
    float* We2s = We1s + 9216;           // 4096
    float* Wc1s = We2s + 4096;           // 4096
    float* Wc2s = Wc1s + 4096;           // 64
    float* be1s = Wc2s + 64;             // 64
    float* be2s = be1s + 64;             // 64
    float* bc1s = be2s + 64;             // 64
    float* wbuf = bc1s + 64;             // 8 * 224

    blk_copy(We1s, We1, 9216);
    blk_copy(We2s, We2, 4096);
    blk_copy(Wc1s, Wc1, 4096);
    blk_copy(Wc2s, Wc2, 64);
    blk_copy(be1s, be1, 64);
    blk_copy(be2s, be2, 64);
    blk_copy(bc1s, bc1, 64);
    __syncthreads();

    const int lane = threadIdx.x & 31;
    const int warp = threadIdx.x >> 5;
    float* cd  = wbuf + warp * 224;      // 16 (12 used)
    float* ein = cd + 16;                // 144
    float* hbf = ein + 144;              // 64

    const float2* We1v = (const float2*)We1s;
    const float2* We2v = (const float2*)We2s;
    const float2* Wc1v = (const float2*)Wc1s;

    const int warp_global = (blockIdx.x * (blockDim.x >> 5)) + warp;
    const int warp_total  = gridDim.x * (blockDim.x >> 5);
    const unsigned FULL = 0xffffffffu;
    const int j0 = 2 * lane, j1 = 2 * lane + 1;

    for (int e = warp_global; e < E; e += warp_total) {
        const int r = row[e];
        const int c = col[e];

        // coord_diff [4,3] -> shared
        if (lane < 12) cd[lane] = Z[r * 12 + lane] - Z[c * 12 + lane];
        __syncwarp();

        // gram (4x4) + l2 normalize -> ein[128..143]
        float g = 0.f;
        if (lane < 16) {
            const float* a = cd + (lane >> 2) * 3;
            const float* b = cd + (lane & 3) * 3;
            g = a[0] * b[0] + a[1] * b[1] + a[2] * b[2];
        }
        float ss = g * g;
        #pragma unroll
        for (int o = 16; o; o >>= 1) ss += __shfl_xor_sync(FULL, ss, o);
        float inv = 1.f / fmaxf(sqrtf(ss), 1e-12f);
        if (lane < 16) ein[128 + lane] = g * inv;

        // gather h[row], h[col]
        ein[lane]       = h[r * 64 + lane];
        ein[lane + 32]  = h[r * 64 + lane + 32];
        ein[64 + lane]  = h[c * 64 + lane];
        ein[96 + lane]  = h[c * 64 + lane + 32];
        __syncwarp();

        // MLP1: 144 -> 64, relu
        float a0 = be1s[j0], a1 = be1s[j1];
        #pragma unroll 16
        for (int k = 0; k < 144; ++k) {
            float x = ein[k];
            float2 w = We1v[k * 32 + lane];
            a0 = fmaf(x, w.x, a0);
            a1 = fmaf(x, w.y, a1);
        }
        a0 = fmaxf(a0, 0.f); a1 = fmaxf(a1, 0.f);
        hbf[j0] = a0; hbf[j1] = a1;
        __syncwarp();

        // MLP2: 64 -> 64, relu  => edge_feat
        float b0 = be2s[j0], b1 = be2s[j1];
        #pragma unroll 16
        for (int k = 0; k < 64; ++k) {
            float x = hbf[k];
            float2 w = We2v[k * 32 + lane];
            b0 = fmaf(x, w.x, b0);
            b1 = fmaf(x, w.y, b1);
        }
        const float ef0 = fmaxf(b0, 0.f);
        const float ef1 = fmaxf(b1, 0.f);
        // stage edge_feat in shared (reuse ein[0..63]; all ein reads finished)
        ein[j0] = ef0; ein[j1] = ef1;
        __syncwarp();

        // coord MLP: relu(ef@Wc1+bc1) @ Wc2 -> phi (scalar)
        float c0 = bc1s[j0], c1v = bc1s[j1];
        #pragma unroll 16
        for (int k = 0; k < 64; ++k) {
            float x = ein[k];
            float2 w = Wc1v[k * 32 + lane];
            c0 = fmaf(x, w.x, c0);
            c1v = fmaf(x, w.y, c1v);
        }
        c0 = fmaxf(c0, 0.f); c1v = fmaxf(c1v, 0.f);
        float ph = c0 * Wc2s[j0] + c1v * Wc2s[j1];
        #pragma unroll
        for (int o = 16; o; o >>= 1) ph += __shfl_xor_sync(FULL, ph, o);

        // scatter
        atomicAdd(&g_agg[r * 64 + j0], ef0);
        atomicAdd(&g_agg[r * 64 + j1], ef1);
        atomicAdd(&g_oth[c * 64 + j0], ef0);
        atomicAdd(&g_oth[c * 64 + j1], ef1);
        if (lane < 12) atomicAdd(&g_seg[r * 12 + lane], cd[lane] * ph);
        if (lane == 0) {
            atomicAdd(&g_cnt_row[r], 1.f);
            atomicAdd(&g_cnt_col[c], 1.f);
        }
        __syncwarp();
    }
}

// ---------------- node kernel: warp per node ----------------
#define NODE_SMEM_FLOATS (12288 + 4096 + 4096 + 64 + 64 + 64 + 64 + 16 + 8 * 256)

__global__ __launch_bounds__(256, 2)
void node_kernel(const float* __restrict__ h, const float* __restrict__ Z,
                 const float* __restrict__ Wn1, const float* __restrict__ bn1,
                 const float* __restrict__ Wn2, const float* __restrict__ bn2,
                 const float* __restrict__ Wv1, const float* __restrict__ bv1,
                 const float* __restrict__ Wv2, const float* __restrict__ bv2,
                 float* __restrict__ out_h, float* __restrict__ out_Z,
                 float* __restrict__ out_x, float* __restrict__ out_v,
                 int n)
{
    extern __shared__ float sm[];
    float* Wn1s = sm;                    // 12288
    float* Wn2s = Wn1s + 12288;          // 4096
    float* Wv1s = Wn2s + 4096;           // 4096
    float* Wv2s = Wv1s + 4096;           // 64
    float* bn1s = Wv2s + 64;             // 64
    float* bn2s = bn1s + 64;             // 64
    float* bv1s = bn2s + 64;             // 64
    float* bv2s = bv1s + 64;             // 16 (1 used)
    float* wbuf = bv2s + 16;             // 8 * 256

    blk_copy(Wn1s, Wn1, 12288);
    blk_copy(Wn2s, Wn2, 4096);
    blk_copy(Wv1s, Wv1, 4096);
    blk_copy(Wv2s, Wv2, 64);
    blk_copy(bn1s, bn1, 64);
    blk_copy(bn2s, bn2, 64);
    blk_copy(bv1s, bv1, 64);
    if (threadIdx.x == 0) bv2s[0] = bv2[0];
    __syncthreads();

    const int lane = threadIdx.x & 31;
    const int warp = threadIdx.x >> 5;
    float* nin = wbuf + warp * 256;      // 192
    float* hbf = nin + 192;              // 64

    const float2* Wn1v = (const float2*)Wn1s;
    const float2* Wn2v = (const float2*)Wn2s;
    const float2* Wv1v = (const float2*)Wv1s;

    const int warp_global = (blockIdx.x * (blockDim.x >> 5)) + warp;
    const int warp_total  = gridDim.x * (blockDim.x >> 5);
    const unsigned FULL = 0xffffffffu;
    const int j0 = 2 * lane, j1 = 2 * lane + 1;

    for (int nd = warp_global; nd < n; nd += warp_total) {
        const float icr = 1.f / fmaxf(g_cnt_row[nd], 1.f);
        const float icc = 1.f / fmaxf(g_cnt_col[nd], 1.f);

        // n_in = [others, h, agg]
        nin[lane]        = g_oth[nd * 64 + lane] * icc;
        nin[lane + 32]   = g_oth[nd * 64 + lane + 32] * icc;
        nin[64 + lane]   = h[nd * 64 + lane];
        nin[96 + lane]   = h[nd * 64 + lane + 32];
        nin[128 + lane]  = g_agg[nd * 64 + lane];
        nin[160 + lane]  = g_agg[nd * 64 + lane + 32];
        __syncwarp();

        // node MLP layer 1: 192 -> 64, relu
        float a0 = bn1s[j0], a1 = bn1s[j1];
        #pragma unroll 16
        for (int k = 0; k < 192; ++k) {
            float x = nin[k];
            float2 w = Wn1v[k * 32 + lane];
            a0 = fmaf(x, w.x, a0);
            a1 = fmaf(x, w.y, a1);
        }
        a0 = fmaxf(a0, 0.f); a1 = fmaxf(a1, 0.f);
        hbf[j0] = a0; hbf[j1] = a1;
        __syncwarp();

        // layer 2 (no relu), residual add
        float b0 = bn2s[j0], b1 = bn2s[j1];
        #pragma unroll 16
        for (int k = 0; k < 64; ++k) {
            float x = hbf[k];
            float2 w = Wn2v[k * 32 + lane];
            b0 = fmaf(x, w.x, b0);
            b1 = fmaf(x, w.y, b1);
        }
        const float hn0 = h[nd * 64 + j0] + b0;
        const float hn1 = h[nd * 64 + j1] + b1;
        out_h[nd * 64 + j0] = hn0;
        out_h[nd * 64 + j1] = hn1;
        // stage h_new for vel MLP (reuse nin[0..63])
        nin[j0] = hn0; nin[j1] = hn1;
        __syncwarp();

        // vel MLP: relu(h_new@Wv1+bv1) @ Wv2 + bv2 -> scale
        float c0 = bv1s[j0], c1v = bv1s[j1];
        #pragma unroll 16
        for (int k = 0; k < 64; ++k) {
            float x = nin[k];
            float2 w = Wv1v[k * 32 + lane];
            c0 = fmaf(x, w.x, c0);
            c1v = fmaf(x, w.y, c1v);
        }
        c0 = fmaxf(c0, 0.f); c1v = fmaxf(c1v, 0.f);
        float sc = c0 * Wv2s[j0] + c1v * Wv2s[j1];
        #pragma unroll
        for (int o = 16; o; o >>= 1) sc += __shfl_xor_sync(FULL, sc, o);
        sc += bv2s[0];

        // coords: f = seg/cnt_row ; Z_new = Z + f
        if (lane < 12) {
            const float fv = g_seg[nd * 12 + lane] * icr;
            const float Zv = Z[nd * 12 + lane];
            out_Z[nd * 12 + lane] = Zv + fv;
            if (lane < 3) {
                const float vcur = Z[nd * 12 + 3 + lane]; // Z[:,1]
                const float vn = sc * vcur + fv;          // f[:,0] = fv for lane<3
                out_v[nd * 3 + lane] = vn;
                out_x[nd * 3 + lane] = Zv + vn;           // Z[:,0] + v_new
            }
        }
        __syncwarp();
    }
}

// ---------------- launch ----------------
extern "C" void kernel_launch(void* const* d_in, const int* in_sizes, int n_in,
                              void* d_out, int out_size)
{
    const float* h   = (const float*)d_in[0];
    const float* Z   = (const float*)d_in[1];
    const int*   row = (const int*)  d_in[2];
    const int*   col = (const int*)  d_in[3];
    const float* We1 = (const float*)d_in[4];
    const float* be1 = (const float*)d_in[5];
    const float* We2 = (const float*)d_in[6];
    const float* be2 = (const float*)d_in[7];
    const float* Wn1 = (const float*)d_in[8];
    const float* bn1 = (const float*)d_in[9];
    const float* Wn2 = (const float*)d_in[10];
    const float* bn2 = (const float*)d_in[11];
    const float* Wc1 = (const float*)d_in[12];
    const float* bc1 = (const float*)d_in[13];
    const float* Wc2 = (const float*)d_in[14];
    const float* Wv1 = (const float*)d_in[15];
    const float* bv1 = (const float*)d_in[16];
    const float* Wv2 = (const float*)d_in[17];
    const float* bv2 = (const float*)d_in[18];

    const int n = in_sizes[0] / 64;     // 50000
    const int E = in_sizes[2];          // 800000

    float* out  = (float*)d_out;
    float* outh = out;                  // [n,64]
    float* outZ = out + (size_t)n * 64; // [n,4,3]
    float* outx = outZ + (size_t)n * 12;// [n,3]
    float* outv = outx + (size_t)n * 3; // [n,3]

    static int attr_done = 0;
    if (!attr_done) {
        cudaFuncSetAttribute(edge_kernel, cudaFuncAttributeMaxDynamicSharedMemorySize,
                             EDGE_SMEM_FLOATS * (int)sizeof(float));
        cudaFuncSetAttribute(node_kernel, cudaFuncAttributeMaxDynamicSharedMemorySize,
                             NODE_SMEM_FLOATS * (int)sizeof(float));
        attr_done = 1;
    }

    zero_scratch<<<512, 256>>>(n);

    edge_kernel<<<296, 256, EDGE_SMEM_FLOATS * sizeof(float)>>>(
        h, Z, row, col, We1, be1, We2, be2, Wc1, bc1, Wc2, E);

    node_kernel<<<296, 256, NODE_SMEM_FLOATS * sizeof(float)>>>(
        h, Z, Wn1, bn1, Wn2, bn2, Wv1, bv1, Wv2, bv2,
        outh, outZ, outx, outv, n);
}

// round 2
// speedup vs baseline: 2.2132x; 2.2132x over previous
#include <cuda_runtime.h>
#include <cuda_bf16.h>
#include <math.h>

#define NNODES 50000
#define FIN    64
#define HID    64

typedef unsigned long long u64;

// ---------------- scratch (device globals; no allocation allowed) ----------------
__device__ float g_seg[NNODES * 12];
__device__ float g_agg[NNODES * 64];
__device__ float g_oth[NNODES * 64];
__device__ float g_cnt_row[NNODES];
__device__ float g_cnt_col[NNODES];

__global__ void zero_scratch(int n) {
    int tid = blockIdx.x * blockDim.x + threadIdx.x;
    int stride = gridDim.x * blockDim.x;
    for (int i = tid; i < n * 64; i += stride) { g_agg[i] = 0.f; g_oth[i] = 0.f; }
    for (int i = tid; i < n * 12; i += stride) g_seg[i] = 0.f;
    for (int i = tid; i < n; i += stride) { g_cnt_row[i] = 0.f; g_cnt_col[i] = 0.f; }
}

__device__ __forceinline__ void blk_copy(float* dst, const float* src, int n) {
    for (int i = threadIdx.x; i < n; i += blockDim.x) dst[i] = src[i];
}

// ---------------- f32x2 packed math helpers ----------------
__device__ __forceinline__ u64 pk2(float x, float y) {
    u64 r; asm("mov.b64 %0, {%1, %2};" : "=l"(r) : "f"(x), "f"(y)); return r;
}
__device__ __forceinline__ float2 upk2(u64 v) {
    float2 f; asm("mov.b64 {%0, %1}, %2;" : "=f"(f.x), "=f"(f.y) : "l"(v)); return f;
}
__device__ __forceinline__ u64 ffma2(u64 a, u64 b, u64 c) {
    u64 d; asm("fma.rn.f32x2 %0, %1, %2, %3;" : "=l"(d) : "l"(a), "l"(b), "l"(c)); return d;
}
__device__ __forceinline__ void red4(float* p, float a, float b, float c, float d) {
    asm volatile("red.global.add.v4.f32 [%0], {%1, %2, %3, %4};"
                 :: "l"(p), "f"(a), "f"(b), "f"(c), "f"(d) : "memory");
}
__device__ __forceinline__ void red1(float* p, float a) {
    asm volatile("red.global.add.f32 [%0], %1;" :: "l"(p), "f"(a) : "memory");
}

// Warp GEMM: [16 edges x K] @ [K x 64] + bias -> acc (f32x2 pairs).
// Lane (mi = lane&3, ni = lane>>2) owns rows mi*4..mi*4+3, cols ni*8..ni*8+7.
template<int K, int AS>
__device__ __forceinline__ void wgemm(const float* __restrict__ A,
                                      const float* __restrict__ W,
                                      const float* __restrict__ bias,
                                      int mi4, int ni8, u64 acc[4][4])
{
    const u64* bp = (const u64*)(bias + ni8);
    u64 b0 = bp[0], b1 = bp[1], b2 = bp[2], b3 = bp[3];
    #pragma unroll
    for (int m = 0; m < 4; m++) { acc[m][0] = b0; acc[m][1] = b1; acc[m][2] = b2; acc[m][3] = b3; }

    #pragma unroll 2
    for (int k = 0; k < K; k++) {
        ulonglong2 wv0 = *(const ulonglong2*)(W + k * 64 + ni8);
        ulonglong2 wv1 = *(const ulonglong2*)(W + k * 64 + ni8 + 4);
        u64 w0 = wv0.x, w1 = wv0.y, w2 = wv1.x, w3 = wv1.y;
        #pragma unroll
        for (int m = 0; m < 4; m++) {
            float x = A[(mi4 + m) * AS + k];
            u64 xp = pk2(x, x);
            acc[m][0] = ffma2(xp, w0, acc[m][0]);
            acc[m][1] = ffma2(xp, w1, acc[m][1]);
            acc[m][2] = ffma2(xp, w2, acc[m][2]);
            acc[m][3] = ffma2(xp, w3, acc[m][3]);
        }
    }
}

// ---------------- edge kernel: 16-edge GEMM tile per warp ----------------
// smem: We1s[144*64] We2s[64*64] Wc1s[64*64] be1s[64] be2s[64] bc1s[64] Wc2s[64]
// per-warp scratch (3632 floats): eins[16*146] act1[16*65] cds[16*13] ridx[16] cidx[16] phis[16]
#define EIN_STRIDE 146
#define WSCR 3632
#define EDGE_SMEM_FLOATS (9216 + 4096 + 4096 + 64 + 64 + 64 + 64 + 8 * WSCR)

__global__ __launch_bounds__(256, 1)
void edge_kernel(const float* __restrict__ h, const float* __restrict__ Z,
                 const int* __restrict__ row, const int* __restrict__ col,
                 const float* __restrict__ We1, const float* __restrict__ be1,
                 const float* __restrict__ We2, const float* __restrict__ be2,
                 const float* __restrict__ Wc1, const float* __restrict__ bc1,
                 const float* __restrict__ Wc2,
                 int E)
{
    extern __shared__ float sm[];
    float* We1s = sm;
    float* We2s = We1s + 9216;
    float* Wc1s = We2s + 4096;
    float* be1s = Wc1s + 4096;
    float* be2s = be1s + 64;
    float* bc1s = be2s + 64;
    float* Wc2s = bc1s + 64;
    float* wscr = Wc2s + 64;

    blk_copy(We1s, We1, 9216);
    blk_copy(We2s, We2, 4096);
    blk_copy(Wc1s, Wc1, 4096);
    blk_copy(be1s, be1, 64);
    blk_copy(be2s, be2, 64);
    blk_copy(bc1s, bc1, 64);
    blk_copy(Wc2s, Wc2, 64);
    __syncthreads();

    const int lane = threadIdx.x & 31;
    const int warp = threadIdx.x >> 5;
    float* eins = wscr + warp * WSCR;       // [16][146]
    float* act1 = eins + 16 * EIN_STRIDE;   // [16][65]
    float* cds  = act1 + 16 * 65;           // [16][13]
    int*   ridx = (int*)(cds + 16 * 13);    // [16]
    int*   cidx = ridx + 16;                // [16]
    float* phis = (float*)(cidx + 16);      // [16]

    const int mi = lane & 3, ni = lane >> 2;
    const int mi4 = mi * 4, ni8 = ni * 8;
    const unsigned FULL = 0xffffffffu;

    const int wg = blockIdx.x * 8 + warp;
    const int nw = gridDim.x * 8;
    const int ntiles = (E + 15) / 16;

    for (int t = wg; t < ntiles; t += nw) {
        const int ebase = t * 16;

        // ---- phase 1: indices, coord_diff, gram, radial (one edge per lane<16) ----
        if (lane < 16) {
            int e = ebase + lane;
            int r = 0, c = 0;
            if (e < E) { r = row[e]; c = col[e]; }
            ridx[lane] = r; cidx[lane] = c;
            float cd[12];
            #pragma unroll
            for (int j = 0; j < 12; j++) {
                cd[j] = Z[r * 12 + j] - Z[c * 12 + j];
                cds[lane * 13 + j] = cd[j];
            }
            float g[16]; float ss = 0.f;
            #pragma unroll
            for (int a = 0; a < 4; a++)
                #pragma unroll
                for (int b = 0; b < 4; b++) {
                    float v = cd[a*3] * cd[b*3] + cd[a*3+1] * cd[b*3+1] + cd[a*3+2] * cd[b*3+2];
                    g[a * 4 + b] = v; ss += v * v;
                }
            float inv = 1.f / fmaxf(sqrtf(ss), 1e-12f);
            #pragma unroll
            for (int j = 0; j < 16; j++) eins[lane * EIN_STRIDE + 128 + j] = g[j] * inv;
        }
        __syncwarp();

        // ---- phase 2: gather h[row], h[col] (L2-resident) ----
        #pragma unroll 4
        for (int m = 0; m < 16; m++) {
            int r = ridx[m], c = cidx[m];
            float2 hr = ((const float2*)(h + r * 64))[lane];
            float2 hc = ((const float2*)(h + c * 64))[lane];
            *(float2*)(eins + m * EIN_STRIDE + 2 * lane) = hr;
            *(float2*)(eins + m * EIN_STRIDE + 64 + 2 * lane) = hc;
        }
        __syncwarp();

        // ---- GEMM1: [16x144]@[144x64] -> relu -> act1 ----
        u64 acc[4][4];
        wgemm<144, EIN_STRIDE>(eins, We1s, be1s, mi4, ni8, acc);
        #pragma unroll
        for (int m = 0; m < 4; m++)
            #pragma unroll
            for (int p = 0; p < 4; p++) {
                float2 v = upk2(acc[m][p]);
                act1[(mi4 + m) * 65 + ni8 + 2 * p]     = fmaxf(v.x, 0.f);
                act1[(mi4 + m) * 65 + ni8 + 2 * p + 1] = fmaxf(v.y, 0.f);
            }
        __syncwarp();

        // ---- GEMM2: [16x64]@[64x64] -> relu -> edge_feat ----
        u64 acc2[4][4];
        wgemm<64, 65>(act1, We2s, be2s, mi4, ni8, acc2);
        float ef[4][8];
        #pragma unroll
        for (int m = 0; m < 4; m++)
            #pragma unroll
            for (int p = 0; p < 4; p++) {
                float2 v = upk2(acc2[m][p]);
                ef[m][2 * p]     = fmaxf(v.x, 0.f);
                ef[m][2 * p + 1] = fmaxf(v.y, 0.f);
            }
        // stage edge_feat (reuse eins region) for coord GEMM
        float* efs = eins;
        #pragma unroll
        for (int m = 0; m < 4; m++)
            #pragma unroll
            for (int cc = 0; cc < 8; cc++)
                efs[(mi4 + m) * 65 + ni8 + cc] = ef[m][cc];
        // scatter agg (row) / oth (col)
        #pragma unroll
        for (int m = 0; m < 4; m++) {
            if (ebase + mi4 + m < E) {
                int r = ridx[mi4 + m], c = cidx[mi4 + m];
                red4(&g_agg[r * 64 + ni8],     ef[m][0], ef[m][1], ef[m][2], ef[m][3]);
                red4(&g_agg[r * 64 + ni8 + 4], ef[m][4], ef[m][5], ef[m][6], ef[m][7]);
                red4(&g_oth[c * 64 + ni8],     ef[m][0], ef[m][1], ef[m][2], ef[m][3]);
                red4(&g_oth[c * 64 + ni8 + 4], ef[m][4], ef[m][5], ef[m][6], ef[m][7]);
            }
        }
        // counts
        if (lane < 16) {
            if (ebase + lane < E) red1(&g_cnt_row[ridx[lane]], 1.f);
        } else {
            int m = lane - 16;
            if (ebase + m < E) red1(&g_cnt_col[cidx[m]], 1.f);
        }
        __syncwarp();

        // ---- GEMM3: coord MLP [16x64]@[64x64] -> relu -> dot Wc2 -> phi ----
        u64 acc3[4][4];
        wgemm<64, 65>(efs, Wc1s, bc1s, mi4, ni8, acc3);
        float2 wc[4];
        {
            const u64* wp = (const u64*)(Wc2s + ni8);
            wc[0] = upk2(wp[0]); wc[1] = upk2(wp[1]); wc[2] = upk2(wp[2]); wc[3] = upk2(wp[3]);
        }
        float part[4];
        #pragma unroll
        for (int m = 0; m < 4; m++) {
            float s = 0.f;
            #pragma unroll
            for (int p = 0; p < 4; p++) {
                float2 v = upk2(acc3[m][p]);
                s += fmaxf(v.x, 0.f) * wc[p].x + fmaxf(v.y, 0.f) * wc[p].y;
            }
            part[m] = s;
        }
        #pragma unroll
        for (int o = 4; o < 32; o <<= 1) {
            #pragma unroll
            for (int m = 0; m < 4; m++) part[m] += __shfl_xor_sync(FULL, part[m], o);
        }
        if (ni == 0) {
            #pragma unroll
            for (int m = 0; m < 4; m++) phis[mi4 + m] = part[m];
        }
        __syncwarp();

        // ---- trans scatter: g_seg[row] += cd * phi ----
        if (lane < 16 && ebase + lane < E) {
            float ph = phis[lane];
            int r = ridx[lane];
            const float* cdp = cds + lane * 13;
            red4(&g_seg[r * 12 + 0], cdp[0] * ph, cdp[1] * ph, cdp[2]  * ph, cdp[3]  * ph);
            red4(&g_seg[r * 12 + 4], cdp[4] * ph, cdp[5] * ph, cdp[6]  * ph, cdp[7]  * ph);
            red4(&g_seg[r * 12 + 8], cdp[8] * ph, cdp[9] * ph, cdp[10] * ph, cdp[11] * ph);
        }
        __syncwarp();
    }
}

// ---------------- node kernel: warp per node (unchanged from R1) ----------------
#define NODE_SMEM_FLOATS (12288 + 4096 + 4096 + 64 + 64 + 64 + 64 + 16 + 8 * 256)

__global__ __launch_bounds__(256, 2)
void node_kernel(const float* __restrict__ h, const float* __restrict__ Z,
                 const float* __restrict__ Wn1, const float* __restrict__ bn1,
                 const float* __restrict__ Wn2, const float* __restrict__ bn2,
                 const float* __restrict__ Wv1, const float* __restrict__ bv1,
                 const float* __restrict__ Wv2, const float* __restrict__ bv2,
                 float* __restrict__ out_h, float* __restrict__ out_Z,
                 float* __restrict__ out_x, float* __restrict__ out_v,
                 int n)
{
    extern __shared__ float sm[];
    float* Wn1s = sm;
    float* Wn2s = Wn1s + 12288;
    float* Wv1s = Wn2s + 4096;
    float* Wv2s = Wv1s + 4096;
    float* bn1s = Wv2s + 64;
    float* bn2s = bn1s + 64;
    float* bv1s = bn2s + 64;
    float* bv2s = bv1s + 64;
    float* wbuf = bv2s + 16;

    blk_copy(Wn1s, Wn1, 12288);
    blk_copy(Wn2s, Wn2, 4096);
    blk_copy(Wv1s, Wv1, 4096);
    blk_copy(Wv2s, Wv2, 64);
    blk_copy(bn1s, bn1, 64);
    blk_copy(bn2s, bn2, 64);
    blk_copy(bv1s, bv1, 64);
    if (threadIdx.x == 0) bv2s[0] = bv2[0];
    __syncthreads();

    const int lane = threadIdx.x & 31;
    const int warp = threadIdx.x >> 5;
    float* nin = wbuf + warp * 256;
    float* hbf = nin + 192;

    const float2* Wn1v = (const float2*)Wn1s;
    const float2* Wn2v = (const float2*)Wn2s;
    const float2* Wv1v = (const float2*)Wv1s;

    const int warp_global = (blockIdx.x * (blockDim.x >> 5)) + warp;
    const int warp_total  = gridDim.x * (blockDim.x >> 5);
    const unsigned FULL = 0xffffffffu;
    const int j0 = 2 * lane, j1 = 2 * lane + 1;

    for (int nd = warp_global; nd < n; nd += warp_total) {
        const float icr = 1.f / fmaxf(g_cnt_row[nd], 1.f);
        const float icc = 1.f / fmaxf(g_cnt_col[nd], 1.f);

        nin[lane]        = g_oth[nd * 64 + lane] * icc;
        nin[lane + 32]   = g_oth[nd * 64 + lane + 32] * icc;
        nin[64 + lane]   = h[nd * 64 + lane];
        nin[96 + lane]   = h[nd * 64 + lane + 32];
        nin[128 + lane]  = g_agg[nd * 64 + lane];
        nin[160 + lane]  = g_agg[nd * 64 + lane + 32];
        __syncwarp();

        float a0 = bn1s[j0], a1 = bn1s[j1];
        #pragma unroll 16
        for (int k = 0; k < 192; ++k) {
            float x = nin[k];
            float2 w = Wn1v[k * 32 + lane];
            a0 = fmaf(x, w.x, a0);
            a1 = fmaf(x, w.y, a1);
        }
        a0 = fmaxf(a0, 0.f); a1 = fmaxf(a1, 0.f);
        hbf[j0] = a0; hbf[j1] = a1;
        __syncwarp();

        float b0 = bn2s[j0], b1 = bn2s[j1];
        #pragma unroll 16
        for (int k = 0; k < 64; ++k) {
            float x = hbf[k];
            float2 w = Wn2v[k * 32 + lane];
            b0 = fmaf(x, w.x, b0);
            b1 = fmaf(x, w.y, b1);
        }
        const float hn0 = h[nd * 64 + j0] + b0;
        const float hn1 = h[nd * 64 + j1] + b1;
        out_h[nd * 64 + j0] = hn0;
        out_h[nd * 64 + j1] = hn1;
        nin[j0] = hn0; nin[j1] = hn1;
        __syncwarp();

        float c0 = bv1s[j0], c1v = bv1s[j1];
        #pragma unroll 16
        for (int k = 0; k < 64; ++k) {
            float x = nin[k];
            float2 w = Wv1v[k * 32 + lane];
            c0 = fmaf(x, w.x, c0);
            c1v = fmaf(x, w.y, c1v);
        }
        c0 = fmaxf(c0, 0.f); c1v = fmaxf(c1v, 0.f);
        float sc = c0 * Wv2s[j0] + c1v * Wv2s[j1];
        #pragma unroll
        for (int o = 16; o; o >>= 1) sc += __shfl_xor_sync(FULL, sc, o);
        sc += bv2s[0];

        if (lane < 12) {
            const float fv = g_seg[nd * 12 + lane] * icr;
            const float Zv = Z[nd * 12 + lane];
            out_Z[nd * 12 + lane] = Zv + fv;
            if (lane < 3) {
                const float vcur = Z[nd * 12 + 3 + lane];
                const float vn = sc * vcur + fv;
                out_v[nd * 3 + lane] = vn;
                out_x[nd * 3 + lane] = Zv + vn;
            }
        }
        __syncwarp();
    }
}

// ---------------- launch ----------------
extern "C" void kernel_launch(void* const* d_in, const int* in_sizes, int n_in,
                              void* d_out, int out_size)
{
    const float* h   = (const float*)d_in[0];
    const float* Z   = (const float*)d_in[1];
    const int*   row = (const int*)  d_in[2];
    const int*   col = (const int*)  d_in[3];
    const float* We1 = (const float*)d_in[4];
    const float* be1 = (const float*)d_in[5];
    const float* We2 = (const float*)d_in[6];
    const float* be2 = (const float*)d_in[7];
    const float* Wn1 = (const float*)d_in[8];
    const float* bn1 = (const float*)d_in[9];
    const float* Wn2 = (const float*)d_in[10];
    const float* bn2 = (const float*)d_in[11];
    const float* Wc1 = (const float*)d_in[12];
    const float* bc1 = (const float*)d_in[13];
    const float* Wc2 = (const float*)d_in[14];
    const float* Wv1 = (const float*)d_in[15];
    const float* bv1 = (const float*)d_in[16];
    const float* Wv2 = (const float*)d_in[17];
    const float* bv2 = (const float*)d_in[18];

    const int n = in_sizes[0] / 64;
    const int E = in_sizes[2];

    float* out  = (float*)d_out;
    float* outh = out;
    float* outZ = out + (size_t)n * 64;
    float* outx = outZ + (size_t)n * 12;
    float* outv = outx + (size_t)n * 3;

    static int attr_done = 0;
    if (!attr_done) {
        cudaFuncSetAttribute(edge_kernel, cudaFuncAttributeMaxDynamicSharedMemorySize,
                             EDGE_SMEM_FLOATS * (int)sizeof(float));
        cudaFuncSetAttribute(node_kernel, cudaFuncAttributeMaxDynamicSharedMemorySize,
                             NODE_SMEM_FLOATS * (int)sizeof(float));
        attr_done = 1;
    }

    zero_scratch<<<512, 256>>>(n);

    edge_kernel<<<148, 256, EDGE_SMEM_FLOATS * sizeof(float)>>>(
        h, Z, row, col, We1, be1, We2, be2, Wc1, bc1, Wc2, E);

    node_kernel<<<296, 256, NODE_SMEM_FLOATS * sizeof(float)>>>(
        h, Z, Wn1, bn1, Wn2, bn2, Wv1, bv1, Wv2, bv2,
        outh, outZ, outx, outv, n);
}

// round 3
// speedup vs baseline: 2.4595x; 1.1113x over previous
#include <cuda_runtime.h>
#include <cuda_bf16.h>
#include <math.h>

#define NNODES 50000
#define FIN    64
#define HID    64

typedef unsigned long long u64;

// ---------------- scratch (device globals; no allocation allowed) ----------------
__device__ float g_seg[NNODES * 12];
__device__ float g_agg[NNODES * 64];
__device__ float g_oth[NNODES * 64];
__device__ float g_cnt_row[NNODES];
__device__ float g_cnt_col[NNODES];

__global__ void zero_scratch(int n) {
    int tid = blockIdx.x * blockDim.x + threadIdx.x;
    int stride = gridDim.x * blockDim.x;
    for (int i = tid; i < n * 64; i += stride) { g_agg[i] = 0.f; g_oth[i] = 0.f; }
    for (int i = tid; i < n * 12; i += stride) g_seg[i] = 0.f;
    for (int i = tid; i < n; i += stride) { g_cnt_row[i] = 0.f; g_cnt_col[i] = 0.f; }
}

__device__ __forceinline__ void blk_copy(float* dst, const float* src, int n) {
    for (int i = threadIdx.x; i < n; i += blockDim.x) dst[i] = src[i];
}

// ---------------- f32x2 packed math + async copy helpers ----------------
__device__ __forceinline__ u64 pk2(float x, float y) {
    u64 r; asm("mov.b64 %0, {%1, %2};" : "=l"(r) : "f"(x), "f"(y)); return r;
}
__device__ __forceinline__ float2 upk2(u64 v) {
    float2 f; asm("mov.b64 {%0, %1}, %2;" : "=f"(f.x), "=f"(f.y) : "l"(v)); return f;
}
__device__ __forceinline__ u64 ffma2(u64 a, u64 b, u64 c) {
    u64 d; asm("fma.rn.f32x2 %0, %1, %2, %3;" : "=l"(d) : "l"(a), "l"(b), "l"(c)); return d;
}
__device__ __forceinline__ void red4(float* p, float a, float b, float c, float d) {
    asm volatile("red.global.add.v4.f32 [%0], {%1, %2, %3, %4};"
                 :: "l"(p), "f"(a), "f"(b), "f"(c), "f"(d) : "memory");
}
__device__ __forceinline__ void red1(float* p, float a) {
    asm volatile("red.global.add.f32 [%0], %1;" :: "l"(p), "f"(a) : "memory");
}
__device__ __forceinline__ void cp16(void* dst_smem, const void* src) {
    unsigned d = (unsigned)__cvta_generic_to_shared(dst_smem);
    asm volatile("cp.async.ca.shared.global [%0], [%1], 16;" :: "r"(d), "l"(src));
}
__device__ __forceinline__ void cp_commit() { asm volatile("cp.async.commit_group;"); }
__device__ __forceinline__ void cp_wait0()  { asm volatile("cp.async.wait_group 0;" ::: "memory"); }

// Warp GEMM: [16 rows x K] @ [K x 64] + bias -> acc (f32x2 pairs).
// Lane (mi = lane&3, ni = lane>>2) owns rows mi*4..+3, cols ni*8..+7.
template<int K, int AS>
__device__ __forceinline__ void wgemm(const float* __restrict__ A,
                                      const float* __restrict__ W,
                                      const float* __restrict__ bias,
                                      int mi4, int ni8, u64 acc[4][4])
{
    const u64* bp = (const u64*)(bias + ni8);
    u64 b0 = bp[0], b1 = bp[1], b2 = bp[2], b3 = bp[3];
    #pragma unroll
    for (int m = 0; m < 4; m++) { acc[m][0] = b0; acc[m][1] = b1; acc[m][2] = b2; acc[m][3] = b3; }

    #pragma unroll 2
    for (int k = 0; k < K; k++) {
        ulonglong2 wv0 = *(const ulonglong2*)(W + k * 64 + ni8);
        ulonglong2 wv1 = *(const ulonglong2*)(W + k * 64 + ni8 + 4);
        u64 w0 = wv0.x, w1 = wv0.y, w2 = wv1.x, w3 = wv1.y;
        #pragma unroll
        for (int m = 0; m < 4; m++) {
            float x = A[(mi4 + m) * AS + k];
            u64 xp = pk2(x, x);
            acc[m][0] = ffma2(xp, w0, acc[m][0]);
            acc[m][1] = ffma2(xp, w1, acc[m][1]);
            acc[m][2] = ffma2(xp, w2, acc[m][2]);
            acc[m][3] = ffma2(xp, w3, acc[m][3]);
        }
    }
}

// ---------------- edge kernel: 16-edge GEMM tile per warp, cp.async gathers ----------------
#define EIN_STRIDE 148
#define EW_SCR (16*EIN_STRIDE + 16*65 + 32 + 16)   // eins + act1 + idxs + phis = 3456
#define EDGE_SMEM_FLOATS (9216 + 4096 + 4096 + 64 + 64 + 64 + 64 + 8 * EW_SCR)

__global__ __launch_bounds__(256, 1)
void edge_kernel(const float* __restrict__ h, const float* __restrict__ Z,
                 const int* __restrict__ row, const int* __restrict__ col,
                 const float* __restrict__ We1, const float* __restrict__ be1,
                 const float* __restrict__ We2, const float* __restrict__ be2,
                 const float* __restrict__ Wc1, const float* __restrict__ bc1,
                 const float* __restrict__ Wc2,
                 int E)
{
    extern __shared__ float sm[];
    float* We1s = sm;
    float* We2s = We1s + 9216;
    float* Wc1s = We2s + 4096;
    float* be1s = Wc1s + 4096;
    float* be2s = be1s + 64;
    float* bc1s = be2s + 64;
    float* Wc2s = bc1s + 64;
    float* wscr = Wc2s + 64;

    blk_copy(We1s, We1, 9216);
    blk_copy(We2s, We2, 4096);
    blk_copy(Wc1s, Wc1, 4096);
    blk_copy(be1s, be1, 64);
    blk_copy(be2s, be2, 64);
    blk_copy(bc1s, bc1, 64);
    blk_copy(Wc2s, Wc2, 64);
    __syncthreads();

    const int lane = threadIdx.x & 31;
    const int warp = threadIdx.x >> 5;
    float* eins = wscr + warp * EW_SCR;          // [16][EIN_STRIDE]
    float* act1 = eins + 16 * EIN_STRIDE;        // [16][65]
    int*   idxs = (int*)(act1 + 16 * 65);        // [32]: 0..15 row, 16..31 col
    float* phis = (float*)(idxs + 32);           // [16]

    const int mi = lane & 3, ni = lane >> 2;
    const int mi4 = mi * 4, ni8 = ni * 8;
    const int sub = lane & 15;
    const bool is_col = lane >= 16;
    const unsigned FULL = 0xffffffffu;

    const int wg = blockIdx.x * 8 + warp;
    const int nw = gridDim.x * 8;
    const int ntiles = (E + 15) / 16;

    for (int t = wg; t < ntiles; t += nw) {
        const int ebase = t * 16;
        const int myedge = ebase + sub;

        // ---- phase A: indices + async h gathers ----
        int idxv = 0;
        if (myedge < E) idxv = is_col ? col[myedge] : row[myedge];
        idxs[lane] = idxv;
        __syncwarp();
        #pragma unroll
        for (int m = 0; m < 16; m++) {
            int node = idxs[is_col ? 16 + m : m];
            cp16(eins + m * EIN_STRIDE + (is_col ? 64 : 0) + sub * 4,
                 h + node * 64 + sub * 4);
        }
        cp_commit();

        // ---- phase B: coord_diff + gram + radial (lanes<16), overlaps gather ----
        float cd[12];
        if (lane < 16) {
            int r = idxs[lane], c = idxs[16 + lane];
            const float4* Zr = (const float4*)(Z + r * 12);
            const float4* Zc = (const float4*)(Z + c * 12);
            #pragma unroll
            for (int q = 0; q < 3; q++) {
                float4 a = Zr[q], b = Zc[q];
                cd[q*4+0] = a.x - b.x; cd[q*4+1] = a.y - b.y;
                cd[q*4+2] = a.z - b.z; cd[q*4+3] = a.w - b.w;
            }
            float g[16]; float ss = 0.f;
            #pragma unroll
            for (int a = 0; a < 4; a++)
                #pragma unroll
                for (int b = 0; b < 4; b++) {
                    float v = cd[a*3]*cd[b*3] + cd[a*3+1]*cd[b*3+1] + cd[a*3+2]*cd[b*3+2];
                    g[a*4+b] = v; ss += v * v;
                }
            float inv = 1.f / fmaxf(sqrtf(ss), 1e-12f);
            #pragma unroll
            for (int j = 0; j < 16; j++) eins[lane * EIN_STRIDE + 128 + j] = g[j] * inv;
        }
        cp_wait0();
        __syncwarp();

        // ---- GEMM1: [16x144]@[144x64] -> relu -> act1 ----
        {
            u64 acc[4][4];
            wgemm<144, EIN_STRIDE>(eins, We1s, be1s, mi4, ni8, acc);
            #pragma unroll
            for (int m = 0; m < 4; m++)
                #pragma unroll
                for (int p = 0; p < 4; p++) {
                    float2 v = upk2(acc[m][p]);
                    act1[(mi4+m)*65 + ni8 + 2*p]     = fmaxf(v.x, 0.f);
                    act1[(mi4+m)*65 + ni8 + 2*p + 1] = fmaxf(v.y, 0.f);
                }
        }
        __syncwarp();

        // ---- GEMM2: [16x64]@[64x64] -> relu -> edge_feat ----
        float ef[4][8];
        {
            u64 acc2[4][4];
            wgemm<64, 65>(act1, We2s, be2s, mi4, ni8, acc2);
            #pragma unroll
            for (int m = 0; m < 4; m++)
                #pragma unroll
                for (int p = 0; p < 4; p++) {
                    float2 v = upk2(acc2[m][p]);
                    ef[m][2*p]   = fmaxf(v.x, 0.f);
                    ef[m][2*p+1] = fmaxf(v.y, 0.f);
                }
        }
        // stage edge_feat into eins (GEMM1 inputs dead) + scatter agg/oth
        #pragma unroll
        for (int m = 0; m < 4; m++) {
            #pragma unroll
            for (int cc = 0; cc < 8; cc++)
                eins[(mi4+m)*EIN_STRIDE + ni8 + cc] = ef[m][cc];
            if (ebase + mi4 + m < E) {
                int r = idxs[mi4 + m], c = idxs[16 + mi4 + m];
                red4(&g_agg[r*64 + ni8],     ef[m][0], ef[m][1], ef[m][2], ef[m][3]);
                red4(&g_agg[r*64 + ni8 + 4], ef[m][4], ef[m][5], ef[m][6], ef[m][7]);
                red4(&g_oth[c*64 + ni8],     ef[m][0], ef[m][1], ef[m][2], ef[m][3]);
                red4(&g_oth[c*64 + ni8 + 4], ef[m][4], ef[m][5], ef[m][6], ef[m][7]);
            }
        }
        if (myedge < E) red1(is_col ? &g_cnt_col[idxv] : &g_cnt_row[idxv], 1.f);
        __syncwarp();

        // ---- GEMM3: coord MLP -> phi ----
        {
            u64 acc3[4][4];
            wgemm<64, EIN_STRIDE>(eins, Wc1s, bc1s, mi4, ni8, acc3);
            float2 wc[4];
            const u64* wp = (const u64*)(Wc2s + ni8);
            wc[0] = upk2(wp[0]); wc[1] = upk2(wp[1]); wc[2] = upk2(wp[2]); wc[3] = upk2(wp[3]);
            float part[4];
            #pragma unroll
            for (int m = 0; m < 4; m++) {
                float s = 0.f;
                #pragma unroll
                for (int p = 0; p < 4; p++) {
                    float2 v = upk2(acc3[m][p]);
                    s += fmaxf(v.x, 0.f) * wc[p].x + fmaxf(v.y, 0.f) * wc[p].y;
                }
                part[m] = s;
            }
            #pragma unroll
            for (int o = 4; o < 32; o <<= 1) {
                #pragma unroll
                for (int m = 0; m < 4; m++) part[m] += __shfl_xor_sync(FULL, part[m], o);
            }
            if (ni == 0) {
                #pragma unroll
                for (int m = 0; m < 4; m++) phis[mi4 + m] = part[m];
            }
        }
        __syncwarp();

        // ---- trans scatter: g_seg[row] += cd * phi (cd still in registers) ----
        if (lane < 16 && myedge < E) {
            float ph = phis[lane];
            int r = idxs[lane];
            red4(&g_seg[r*12 + 0], cd[0]*ph, cd[1]*ph, cd[2]*ph,  cd[3]*ph);
            red4(&g_seg[r*12 + 4], cd[4]*ph, cd[5]*ph, cd[6]*ph,  cd[7]*ph);
            red4(&g_seg[r*12 + 8], cd[8]*ph, cd[9]*ph, cd[10]*ph, cd[11]*ph);
        }
        __syncwarp();
    }
}

// ---------------- node kernel: 16-node GEMM tile per warp ----------------
#define NIN_STRIDE 196
#define NW_SCR (16*NIN_STRIDE + 16*65 + 16 + 16)   // nins + act1 + iccs + scs = 4208
#define NODE_SMEM_FLOATS (12288 + 4096 + 4096 + 64 + 64 + 64 + 64 + 16 + 8 * NW_SCR)

__global__ __launch_bounds__(256, 1)
void node_kernel(const float* __restrict__ h, const float* __restrict__ Z,
                 const float* __restrict__ Wn1, const float* __restrict__ bn1,
                 const float* __restrict__ Wn2, const float* __restrict__ bn2,
                 const float* __restrict__ Wv1, const float* __restrict__ bv1,
                 const float* __restrict__ Wv2, const float* __restrict__ bv2,
                 float* __restrict__ out_h, float* __restrict__ out_Z,
                 float* __restrict__ out_x, float* __restrict__ out_v,
                 int n)
{
    extern __shared__ float sm[];
    float* Wn1s = sm;
    float* Wn2s = Wn1s + 12288;
    float* Wv1s = Wn2s + 4096;
    float* Wv2s = Wv1s + 4096;
    float* bn1s = Wv2s + 64;
    float* bn2s = bn1s + 64;
    float* bv1s = bn2s + 64;
    float* bv2s = bv1s + 64;     // 16 floats reserved, 1 used
    float* wscr = bv2s + 16;

    blk_copy(Wn1s, Wn1, 12288);
    blk_copy(Wn2s, Wn2, 4096);
    blk_copy(Wv1s, Wv1, 4096);
    blk_copy(Wv2s, Wv2, 64);
    blk_copy(bn1s, bn1, 64);
    blk_copy(bn2s, bn2, 64);
    blk_copy(bv1s, bv1, 64);
    if (threadIdx.x == 0) bv2s[0] = bv2[0];
    __syncthreads();

    const int lane = threadIdx.x & 31;
    const int warp = threadIdx.x >> 5;
    float* nins = wscr + warp * NW_SCR;          // [16][NIN_STRIDE]
    float* act1 = nins + 16 * NIN_STRIDE;        // [16][65]
    float* iccs = act1 + 16 * 65;                // [16]
    float* scs  = iccs + 16;                     // [16]

    const int mi = lane & 3, ni = lane >> 2;
    const int mi4 = mi * 4, ni8 = ni * 8;
    const int sub = lane & 15;
    const int half = lane >> 4;
    const unsigned FULL = 0xffffffffu;

    const int wg = blockIdx.x * 8 + warp;
    const int nw = gridDim.x * 8;
    const int ntiles = (n + 15) / 16;

    for (int t = wg; t < ntiles; t += nw) {
        const int nbase = t * 16;

        float icr = 1.f;
        if (lane < 16) {
            int nd = nbase + lane; if (nd >= n) nd = n - 1;
            icr = 1.f / fmaxf(g_cnt_row[nd], 1.f);
            iccs[lane] = 1.f / fmaxf(g_cnt_col[nd], 1.f);
        }

        // async gathers: oth / h / agg rows (16B chunks, coalesced)
        #pragma unroll
        for (int mm = 0; mm < 8; mm++) {
            int m = 2 * mm + half;
            int nd = nbase + m; if (nd >= n) nd = n - 1;
            cp16(nins + m*NIN_STRIDE + sub*4,        g_oth + nd*64 + sub*4);
            cp16(nins + m*NIN_STRIDE + 64 + sub*4,  h     + nd*64 + sub*4);
            cp16(nins + m*NIN_STRIDE + 128 + sub*4, g_agg + nd*64 + sub*4);
        }
        cp_commit();
        cp_wait0();
        __syncwarp();

        // scale oth region by icc (row m = lane>>1, half row each)
        {
            int m = lane >> 1;
            float icc = iccs[m];
            float4* p = (float4*)(nins + m*NIN_STRIDE + (lane & 1) * 32);
            #pragma unroll
            for (int q = 0; q < 8; q++) {
                float4 v = p[q];
                v.x *= icc; v.y *= icc; v.z *= icc; v.w *= icc;
                p[q] = v;
            }
        }
        __syncwarp();

        // GEMM1: [16x192]@[192x64] -> relu -> act1
        {
            u64 acc[4][4];
            wgemm<192, NIN_STRIDE>(nins, Wn1s, bn1s, mi4, ni8, acc);
            #pragma unroll
            for (int m = 0; m < 4; m++)
                #pragma unroll
                for (int p = 0; p < 4; p++) {
                    float2 v = upk2(acc[m][p]);
                    act1[(mi4+m)*65 + ni8 + 2*p]     = fmaxf(v.x, 0.f);
                    act1[(mi4+m)*65 + ni8 + 2*p + 1] = fmaxf(v.y, 0.f);
                }
        }
        __syncwarp();

        // GEMM2: [16x64]@[64x64] + h residual -> h_new ; store + stage
        {
            u64 acc2[4][4];
            wgemm<64, 65>(act1, Wn2s, bn2s, mi4, ni8, acc2);
            #pragma unroll
            for (int m = 0; m < 4; m++) {
                int nd = nbase + mi4 + m;
                float4 h0 = *(float4*)(nins + (mi4+m)*NIN_STRIDE + 64 + ni8);
                float4 h1 = *(float4*)(nins + (mi4+m)*NIN_STRIDE + 64 + ni8 + 4);
                float2 v0 = upk2(acc2[m][0]), v1 = upk2(acc2[m][1]);
                float2 v2 = upk2(acc2[m][2]), v3 = upk2(acc2[m][3]);
                float4 hn0 = make_float4(h0.x + v0.x, h0.y + v0.y, h0.z + v1.x, h0.w + v1.y);
                float4 hn1 = make_float4(h1.x + v2.x, h1.y + v2.y, h1.z + v3.x, h1.w + v3.y);
                if (nd < n) {
                    *(float4*)(out_h + nd*64 + ni8)     = hn0;
                    *(float4*)(out_h + nd*64 + ni8 + 4) = hn1;
                }
                *(float4*)(nins + (mi4+m)*NIN_STRIDE + ni8)     = hn0;
                *(float4*)(nins + (mi4+m)*NIN_STRIDE + ni8 + 4) = hn1;
            }
        }
        __syncwarp();

        // GEMM3 (vel): relu(h_new@Wv1+bv1) . Wv2 -> scale
        {
            u64 acc3[4][4];
            wgemm<64, NIN_STRIDE>(nins, Wv1s, bv1s, mi4, ni8, acc3);
            float2 wv[4];
            const u64* wp = (const u64*)(Wv2s + ni8);
            wv[0] = upk2(wp[0]); wv[1] = upk2(wp[1]); wv[2] = upk2(wp[2]); wv[3] = upk2(wp[3]);
            float part[4];
            #pragma unroll
            for (int m = 0; m < 4; m++) {
                float s = 0.f;
                #pragma unroll
                for (int p = 0; p < 4; p++) {
                    float2 v = upk2(acc3[m][p]);
                    s += fmaxf(v.x, 0.f) * wv[p].x + fmaxf(v.y, 0.f) * wv[p].y;
                }
                part[m] = s;
            }
            #pragma unroll
            for (int o = 4; o < 32; o <<= 1) {
                #pragma unroll
                for (int m = 0; m < 4; m++) part[m] += __shfl_xor_sync(FULL, part[m], o);
            }
            if (ni == 0) {
                #pragma unroll
                for (int m = 0; m < 4; m++) scs[mi4 + m] = part[m];
            }
        }
        __syncwarp();

        // epilogue: coords + vel (lanes<16, one node each)
        if (lane < 16) {
            int nd = nbase + lane;
            if (nd < n) {
                float sc = scs[lane] + bv2s[0];
                #pragma unroll
                for (int q = 0; q < 3; q++) {
                    float4 sg = *(const float4*)(g_seg + nd*12 + q*4);
                    float4 Zv = *(const float4*)(Z + nd*12 + q*4);
                    float4 f  = make_float4(sg.x*icr, sg.y*icr, sg.z*icr, sg.w*icr);
                    *(float4*)(out_Z + nd*12 + q*4) =
                        make_float4(Zv.x+f.x, Zv.y+f.y, Zv.z+f.z, Zv.w+f.w);
                    if (q == 0) {
                        // v_new = sc*Z[:,1] + f[:,0]; x_new = Z[:,0] + v_new
                        float v0 = sc * Z[nd*12 + 3] + f.x;
                        float v1 = sc * Z[nd*12 + 4] + f.y;
                        float v2 = sc * Z[nd*12 + 5] + f.z;
                        out_v[nd*3 + 0] = v0; out_v[nd*3 + 1] = v1; out_v[nd*3 + 2] = v2;
                        out_x[nd*3 + 0] = Zv.x + v0;
                        out_x[nd*3 + 1] = Zv.y + v1;
                        out_x[nd*3 + 2] = Zv.z + v2;
                    }
                }
            }
        }
        __syncwarp();
    }
}

// ---------------- launch ----------------
extern "C" void kernel_launch(void* const* d_in, const int* in_sizes, int n_in,
                              void* d_out, int out_size)
{
    const float* h   = (const float*)d_in[0];
    const float* Z   = (const float*)d_in[1];
    const int*   row = (const int*)  d_in[2];
    const int*   col = (const int*)  d_in[3];
    const float* We1 = (const float*)d_in[4];
    const float* be1 = (const float*)d_in[5];
    const float* We2 = (const float*)d_in[6];
    const float* be2 = (const float*)d_in[7];
    const float* Wn1 = (const float*)d_in[8];
    const float* bn1 = (const float*)d_in[9];
    const float* Wn2 = (const float*)d_in[10];
    const float* bn2 = (const float*)d_in[11];
    const float* Wc1 = (const float*)d_in[12];
    const float* bc1 = (const float*)d_in[13];
    const float* Wc2 = (const float*)d_in[14];
    const float* Wv1 = (const float*)d_in[15];
    const float* bv1 = (const float*)d_in[16];
    const float* Wv2 = (const float*)d_in[17];
    const float* bv2 = (const float*)d_in[18];

    const int n = in_sizes[0] / 64;
    const int E = in_sizes[2];

    float* out  = (float*)d_out;
    float* outh = out;
    float* outZ = out + (size_t)n * 64;
    float* outx = outZ + (size_t)n * 12;
    float* outv = outx + (size_t)n * 3;

    static int attr_done = 0;
    if (!attr_done) {
        cudaFuncSetAttribute(edge_kernel, cudaFuncAttributeMaxDynamicSharedMemorySize,
                             EDGE_SMEM_FLOATS * (int)sizeof(float));
        cudaFuncSetAttribute(node_kernel, cudaFuncAttributeMaxDynamicSharedMemorySize,
                             NODE_SMEM_FLOATS * (int)sizeof(float));
        attr_done = 1;
    }

    zero_scratch<<<512, 256>>>(n);

    edge_kernel<<<148, 256, EDGE_SMEM_FLOATS * sizeof(float)>>>(
        h, Z, row, col, We1, be1, We2, be2, Wc1, bc1, Wc2, E);

    node_kernel<<<148, 256, NODE_SMEM_FLOATS * sizeof(float)>>>(
        h, Z, Wn1, bn1, Wn2, bn2, Wv1, bv1, Wv2, bv2,
        outh, outZ, outx, outv, n);
}

// round 4
// speedup vs baseline: 2.7694x; 1.1260x over previous
#include <cuda_runtime.h>
#include <cuda_bf16.h>
#include <math.h>

#define NNODES 50000
#define FIN    64
#define HID    64

typedef unsigned long long u64;

// ---------------- scratch (device globals; no allocation allowed) ----------------
__device__ float g_seg[NNODES * 12];
__device__ float g_agg[NNODES * 64];
__device__ float g_oth[NNODES * 64];
__device__ float g_cnt_row[NNODES];
__device__ float g_cnt_col[NNODES];

__global__ void zero_scratch(int n) {
    int tid = blockIdx.x * blockDim.x + threadIdx.x;
    int stride = gridDim.x * blockDim.x;
    for (int i = tid; i < n * 64; i += stride) { g_agg[i] = 0.f; g_oth[i] = 0.f; }
    for (int i = tid; i < n * 12; i += stride) g_seg[i] = 0.f;
    for (int i = tid; i < n; i += stride) { g_cnt_row[i] = 0.f; g_cnt_col[i] = 0.f; }
}

__device__ __forceinline__ void blk_copy(float* dst, const float* src, int n) {
    for (int i = threadIdx.x; i < n; i += blockDim.x) dst[i] = src[i];
}

// ---------------- f32x2 packed math + async copy helpers ----------------
__device__ __forceinline__ u64 pk2(float x, float y) {
    u64 r; asm("mov.b64 %0, {%1, %2};" : "=l"(r) : "f"(x), "f"(y)); return r;
}
__device__ __forceinline__ float2 upk2(u64 v) {
    float2 f; asm("mov.b64 {%0, %1}, %2;" : "=f"(f.x), "=f"(f.y) : "l"(v)); return f;
}
__device__ __forceinline__ u64 ffma2(u64 a, u64 b, u64 c) {
    u64 d; asm("fma.rn.f32x2 %0, %1, %2, %3;" : "=l"(d) : "l"(a), "l"(b), "l"(c)); return d;
}
__device__ __forceinline__ void red4(float* p, float a, float b, float c, float d) {
    asm volatile("red.global.add.v4.f32 [%0], {%1, %2, %3, %4};"
                 :: "l"(p), "f"(a), "f"(b), "f"(c), "f"(d) : "memory");
}
__device__ __forceinline__ void red1(float* p, float a) {
    asm volatile("red.global.add.f32 [%0], %1;" :: "l"(p), "f"(a) : "memory");
}
__device__ __forceinline__ void cp16(void* dst_smem, const void* src) {
    unsigned d = (unsigned)__cvta_generic_to_shared(dst_smem);
    asm volatile("cp.async.ca.shared.global [%0], [%1], 16;" :: "r"(d), "l"(src));
}
__device__ __forceinline__ void cp_commit() { asm volatile("cp.async.commit_group;"); }
__device__ __forceinline__ void cp_wait0()  { asm volatile("cp.async.wait_group 0;" ::: "memory"); }

// Warp GEMM: [MR*4 rows x K] @ [K x 64] + bias -> acc (f32x2 pairs).
// Lane (mi = lane&3, ni = lane>>2) owns rows mi*MR..+MR-1, cols ni*8..+7.
template<int K, int AS, int MR>
__device__ __forceinline__ void wgemm(const float* __restrict__ A,
                                      const float* __restrict__ W,
                                      const float* __restrict__ bias,
                                      int mrow0, int ni8, u64 acc[MR][4])
{
    const u64* bp = (const u64*)(bias + ni8);
    u64 b0 = bp[0], b1 = bp[1], b2 = bp[2], b3 = bp[3];
    #pragma unroll
    for (int m = 0; m < MR; m++) { acc[m][0] = b0; acc[m][1] = b1; acc[m][2] = b2; acc[m][3] = b3; }

    #pragma unroll 2
    for (int k = 0; k < K; k++) {
        ulonglong2 wv0 = *(const ulonglong2*)(W + k * 64 + ni8);
        ulonglong2 wv1 = *(const ulonglong2*)(W + k * 64 + ni8 + 4);
        u64 w0 = wv0.x, w1 = wv0.y, w2 = wv1.x, w3 = wv1.y;
        #pragma unroll
        for (int m = 0; m < MR; m++) {
            float x = A[(mrow0 + m) * AS + k];
            u64 xp = pk2(x, x);
            acc[m][0] = ffma2(xp, w0, acc[m][0]);
            acc[m][1] = ffma2(xp, w1, acc[m][1]);
            acc[m][2] = ffma2(xp, w2, acc[m][2]);
            acc[m][3] = ffma2(xp, w3, acc[m][3]);
        }
    }
}

// ---------------- edge kernel: 512 threads, 16 warps, 16-edge tile per warp ----------------
#define EIN_STRIDE 148
#define EW_SCR (16*EIN_STRIDE + 32 + 16)   // eins + idxs + phis = 2416
#define EDGE_SMEM_FLOATS (9216 + 4096 + 4096 + 64 + 64 + 64 + 64 + 16 * EW_SCR)

__global__ __launch_bounds__(512, 1)
void edge_kernel(const float* __restrict__ h, const float* __restrict__ Z,
                 const int* __restrict__ row, const int* __restrict__ col,
                 const float* __restrict__ We1, const float* __restrict__ be1,
                 const float* __restrict__ We2, const float* __restrict__ be2,
                 const float* __restrict__ Wc1, const float* __restrict__ bc1,
                 const float* __restrict__ Wc2,
                 int E)
{
    extern __shared__ float sm[];
    float* We1s = sm;
    float* We2s = We1s + 9216;
    float* Wc1s = We2s + 4096;
    float* be1s = Wc1s + 4096;
    float* be2s = be1s + 64;
    float* bc1s = be2s + 64;
    float* Wc2s = bc1s + 64;
    float* wscr = Wc2s + 64;

    blk_copy(We1s, We1, 9216);
    blk_copy(We2s, We2, 4096);
    blk_copy(Wc1s, Wc1, 4096);
    blk_copy(be1s, be1, 64);
    blk_copy(be2s, be2, 64);
    blk_copy(bc1s, bc1, 64);
    blk_copy(Wc2s, Wc2, 64);
    __syncthreads();

    const int lane = threadIdx.x & 31;
    const int warp = threadIdx.x >> 5;
    float* eins = wscr + warp * EW_SCR;          // [16][EIN_STRIDE]
    int*   idxs = (int*)(eins + 16 * EIN_STRIDE);// [32]: 0..15 row, 16..31 col
    float* phis = (float*)(idxs + 32);           // [16]

    const int mi = lane & 3, ni = lane >> 2;
    const int mi4 = mi * 4, ni8 = ni * 8;
    const int sub = lane & 15;
    const bool is_col = lane >= 16;
    const unsigned FULL = 0xffffffffu;

    const int wg = blockIdx.x * 16 + warp;
    const int nw = gridDim.x * 16;
    const int ntiles = (E + 15) / 16;

    for (int t = wg; t < ntiles; t += nw) {
        const int ebase = t * 16;
        const int myedge = ebase + sub;

        // ---- phase A: indices + async h gathers (cols 0..127) ----
        int idxv = 0;
        if (myedge < E) idxv = is_col ? col[myedge] : row[myedge];
        idxs[lane] = idxv;
        __syncwarp();
        #pragma unroll
        for (int m = 0; m < 16; m++) {
            int node = idxs[is_col ? 16 + m : m];
            cp16(eins + m * EIN_STRIDE + (is_col ? 64 : 0) + sub * 4,
                 h + node * 64 + sub * 4);
        }
        cp_commit();

        // ---- phase B: coord_diff + gram + radial (lanes<16) -> cols 128..143 ----
        float cd[12];
        if (lane < 16) {
            int r = idxs[lane], c = idxs[16 + lane];
            const float4* Zr = (const float4*)(Z + r * 12);
            const float4* Zc = (const float4*)(Z + c * 12);
            #pragma unroll
            for (int q = 0; q < 3; q++) {
                float4 a = Zr[q], b = Zc[q];
                cd[q*4+0] = a.x - b.x; cd[q*4+1] = a.y - b.y;
                cd[q*4+2] = a.z - b.z; cd[q*4+3] = a.w - b.w;
            }
            float g[16]; float ss = 0.f;
            #pragma unroll
            for (int a = 0; a < 4; a++)
                #pragma unroll
                for (int b = 0; b < 4; b++) {
                    float v = cd[a*3]*cd[b*3] + cd[a*3+1]*cd[b*3+1] + cd[a*3+2]*cd[b*3+2];
                    g[a*4+b] = v; ss += v * v;
                }
            float inv = 1.f / fmaxf(sqrtf(ss), 1e-12f);
            #pragma unroll
            for (int j = 0; j < 16; j++) eins[lane * EIN_STRIDE + 128 + j] = g[j] * inv;
        }
        cp_wait0();
        __syncwarp();

        // ---- GEMM1: [16x144]@[144x64] -> relu -> (sync) cols 64..127 ----
        {
            u64 acc[4][4];
            wgemm<144, EIN_STRIDE, 4>(eins, We1s, be1s, mi4, ni8, acc);
            __syncwarp();       // all lanes done reading cols 0..143
            #pragma unroll
            for (int m = 0; m < 4; m++)
                #pragma unroll
                for (int p = 0; p < 4; p++) {
                    float2 v = upk2(acc[m][p]);
                    eins[(mi4+m)*EIN_STRIDE + 64 + ni8 + 2*p]     = fmaxf(v.x, 0.f);
                    eins[(mi4+m)*EIN_STRIDE + 64 + ni8 + 2*p + 1] = fmaxf(v.y, 0.f);
                }
        }
        __syncwarp();

        // ---- GEMM2: [16x64]@[64x64] -> relu -> edge_feat; stage to cols 0..63 ----
        float ef[4][8];
        {
            u64 acc2[4][4];
            wgemm<64, EIN_STRIDE, 4>(eins + 64, We2s, be2s, mi4, ni8, acc2);
            #pragma unroll
            for (int m = 0; m < 4; m++)
                #pragma unroll
                for (int p = 0; p < 4; p++) {
                    float2 v = upk2(acc2[m][p]);
                    ef[m][2*p]   = fmaxf(v.x, 0.f);
                    ef[m][2*p+1] = fmaxf(v.y, 0.f);
                }
        }
        #pragma unroll
        for (int m = 0; m < 4; m++) {
            #pragma unroll
            for (int cc = 0; cc < 8; cc++)
                eins[(mi4+m)*EIN_STRIDE + ni8 + cc] = ef[m][cc];  // disjoint from cols 64..127
            if (ebase + mi4 + m < E) {
                int r = idxs[mi4 + m], c = idxs[16 + mi4 + m];
                red4(&g_agg[r*64 + ni8],     ef[m][0], ef[m][1], ef[m][2], ef[m][3]);
                red4(&g_agg[r*64 + ni8 + 4], ef[m][4], ef[m][5], ef[m][6], ef[m][7]);
                red4(&g_oth[c*64 + ni8],     ef[m][0], ef[m][1], ef[m][2], ef[m][3]);
                red4(&g_oth[c*64 + ni8 + 4], ef[m][4], ef[m][5], ef[m][6], ef[m][7]);
            }
        }
        if (myedge < E) red1(is_col ? &g_cnt_col[idxv] : &g_cnt_row[idxv], 1.f);
        __syncwarp();

        // ---- GEMM3: coord MLP (reads cols 0..63) -> phi ----
        {
            u64 acc3[4][4];
            wgemm<64, EIN_STRIDE, 4>(eins, Wc1s, bc1s, mi4, ni8, acc3);
            float2 wc[4];
            const u64* wp = (const u64*)(Wc2s + ni8);
            wc[0] = upk2(wp[0]); wc[1] = upk2(wp[1]); wc[2] = upk2(wp[2]); wc[3] = upk2(wp[3]);
            float part[4];
            #pragma unroll
            for (int m = 0; m < 4; m++) {
                float s = 0.f;
                #pragma unroll
                for (int p = 0; p < 4; p++) {
                    float2 v = upk2(acc3[m][p]);
                    s += fmaxf(v.x, 0.f) * wc[p].x + fmaxf(v.y, 0.f) * wc[p].y;
                }
                part[m] = s;
            }
            #pragma unroll
            for (int o = 4; o < 32; o <<= 1) {
                #pragma unroll
                for (int m = 0; m < 4; m++) part[m] += __shfl_xor_sync(FULL, part[m], o);
            }
            if (ni == 0) {
                #pragma unroll
                for (int m = 0; m < 4; m++) phis[mi4 + m] = part[m];
            }
        }
        __syncwarp();

        // ---- trans scatter: g_seg[row] += cd * phi (cd in registers) ----
        if (lane < 16 && myedge < E) {
            float ph = phis[lane];
            int r = idxs[lane];
            red4(&g_seg[r*12 + 0], cd[0]*ph, cd[1]*ph, cd[2]*ph,  cd[3]*ph);
            red4(&g_seg[r*12 + 4], cd[4]*ph, cd[5]*ph, cd[6]*ph,  cd[7]*ph);
            red4(&g_seg[r*12 + 8], cd[8]*ph, cd[9]*ph, cd[10]*ph, cd[11]*ph);
        }
        __syncwarp();
    }
}

// ---------------- node kernel: 512 threads, 16 warps, 8-node tile per warp ----------------
#define NIN_STRIDE 196
#define NW_SCR (8*NIN_STRIDE + 8 + 8)    // nins + iccs + scs = 1584
#define NODE_SMEM_FLOATS (12288 + 4096 + 4096 + 64 + 64 + 64 + 64 + 16 + 16 * NW_SCR)

__global__ __launch_bounds__(512, 1)
void node_kernel(const float* __restrict__ h, const float* __restrict__ Z,
                 const float* __restrict__ Wn1, const float* __restrict__ bn1,
                 const float* __restrict__ Wn2, const float* __restrict__ bn2,
                 const float* __restrict__ Wv1, const float* __restrict__ bv1,
                 const float* __restrict__ Wv2, const float* __restrict__ bv2,
                 float* __restrict__ out_h, float* __restrict__ out_Z,
                 float* __restrict__ out_x, float* __restrict__ out_v,
                 int n)
{
    extern __shared__ float sm[];
    float* Wn1s = sm;
    float* Wn2s = Wn1s + 12288;
    float* Wv1s = Wn2s + 4096;
    float* Wv2s = Wv1s + 4096;
    float* bn1s = Wv2s + 64;
    float* bn2s = bn1s + 64;
    float* bv1s = bn2s + 64;
    float* bv2s = bv1s + 64;     // 16 floats reserved, 1 used
    float* wscr = bv2s + 16;

    blk_copy(Wn1s, Wn1, 12288);
    blk_copy(Wn2s, Wn2, 4096);
    blk_copy(Wv1s, Wv1, 4096);
    blk_copy(Wv2s, Wv2, 64);
    blk_copy(bn1s, bn1, 64);
    blk_copy(bn2s, bn2, 64);
    blk_copy(bv1s, bv1, 64);
    if (threadIdx.x == 0) bv2s[0] = bv2[0];
    __syncthreads();

    const int lane = threadIdx.x & 31;
    const int warp = threadIdx.x >> 5;
    float* nins = wscr + warp * NW_SCR;          // [8][NIN_STRIDE]
    float* iccs = nins + 8 * NIN_STRIDE;         // [8]
    float* scs  = iccs + 8;                      // [8]

    const int mi = lane & 3, ni = lane >> 2;
    const int mi2 = mi * 2, ni8 = ni * 8;
    const int sub = lane & 15;
    const int half = lane >> 4;
    const unsigned FULL = 0xffffffffu;

    const int wg = blockIdx.x * 16 + warp;
    const int nw = gridDim.x * 16;
    const int ntiles = (n + 7) / 8;

    for (int t = wg; t < ntiles; t += nw) {
        const int nbase = t * 8;

        float icr = 1.f;
        if (lane < 8) {
            int nd = nbase + lane; if (nd >= n) nd = n - 1;
            icr = 1.f / fmaxf(g_cnt_row[nd], 1.f);
            iccs[lane] = 1.f / fmaxf(g_cnt_col[nd], 1.f);
        }

        // async gathers: oth(0..63) / h(64..127) / agg(128..191)
        #pragma unroll
        for (int mm = 0; mm < 4; mm++) {
            int m = 2 * mm + half;
            int nd = nbase + m; if (nd >= n) nd = n - 1;
            cp16(nins + m*NIN_STRIDE + sub*4,        g_oth + nd*64 + sub*4);
            cp16(nins + m*NIN_STRIDE + 64 + sub*4,  h     + nd*64 + sub*4);
            cp16(nins + m*NIN_STRIDE + 128 + sub*4, g_agg + nd*64 + sub*4);
        }
        cp_commit();
        cp_wait0();
        __syncwarp();

        // scale oth region by icc: lane handles row lane>>2, 16-col quarter (lane&3)
        {
            int m = lane >> 2;
            float icc = iccs[m];
            float4* p = (float4*)(nins + m*NIN_STRIDE + (lane & 3) * 16);
            #pragma unroll
            for (int q = 0; q < 4; q++) {
                float4 v = p[q];
                v.x *= icc; v.y *= icc; v.z *= icc; v.w *= icc;
                p[q] = v;
            }
        }
        __syncwarp();

        // GEMM1: [8x192]@[192x64] -> relu -> (sync) cols 0..63
        {
            u64 acc[2][4];
            wgemm<192, NIN_STRIDE, 2>(nins, Wn1s, bn1s, mi2, ni8, acc);
            __syncwarp();
            #pragma unroll
            for (int m = 0; m < 2; m++)
                #pragma unroll
                for (int p = 0; p < 4; p++) {
                    float2 v = upk2(acc[m][p]);
                    nins[(mi2+m)*NIN_STRIDE + ni8 + 2*p]     = fmaxf(v.x, 0.f);
                    nins[(mi2+m)*NIN_STRIDE + ni8 + 2*p + 1] = fmaxf(v.y, 0.f);
                }
        }
        __syncwarp();

        // GEMM2: [8x64]@[64x64] + h residual -> h_new; store + stage cols 128..191
        {
            u64 acc2[2][4];
            wgemm<64, NIN_STRIDE, 2>(nins, Wn2s, bn2s, mi2, ni8, acc2);
            #pragma unroll
            for (int m = 0; m < 2; m++) {
                int nd = nbase + mi2 + m;
                float4 h0 = *(float4*)(nins + (mi2+m)*NIN_STRIDE + 64 + ni8);
                float4 h1 = *(float4*)(nins + (mi2+m)*NIN_STRIDE + 64 + ni8 + 4);
                float2 v0 = upk2(acc2[m][0]), v1 = upk2(acc2[m][1]);
                float2 v2 = upk2(acc2[m][2]), v3 = upk2(acc2[m][3]);
                float4 hn0 = make_float4(h0.x + v0.x, h0.y + v0.y, h0.z + v1.x, h0.w + v1.y);
                float4 hn1 = make_float4(h1.x + v2.x, h1.y + v2.y, h1.z + v3.x, h1.w + v3.y);
                if (nd < n) {
                    *(float4*)(out_h + nd*64 + ni8)     = hn0;
                    *(float4*)(out_h + nd*64 + ni8 + 4) = hn1;
                }
                *(float4*)(nins + (mi2+m)*NIN_STRIDE + 128 + ni8)     = hn0;
                *(float4*)(nins + (mi2+m)*NIN_STRIDE + 128 + ni8 + 4) = hn1;
            }
        }
        __syncwarp();

        // GEMM3 (vel): relu(h_new@Wv1+bv1) . Wv2 -> scale
        {
            u64 acc3[2][4];
            wgemm<64, NIN_STRIDE, 2>(nins + 128, Wv1s, bv1s, mi2, ni8, acc3);
            float2 wv[4];
            const u64* wp = (const u64*)(Wv2s + ni8);
            wv[0] = upk2(wp[0]); wv[1] = upk2(wp[1]); wv[2] = upk2(wp[2]); wv[3] = upk2(wp[3]);
            float part[2];
            #pragma unroll
            for (int m = 0; m < 2; m++) {
                float s = 0.f;
                #pragma unroll
                for (int p = 0; p < 4; p++) {
                    float2 v = upk2(acc3[m][p]);
                    s += fmaxf(v.x, 0.f) * wv[p].x + fmaxf(v.y, 0.f) * wv[p].y;
                }
                part[m] = s;
            }
            #pragma unroll
            for (int o = 4; o < 32; o <<= 1) {
                #pragma unroll
                for (int m = 0; m < 2; m++) part[m] += __shfl_xor_sync(FULL, part[m], o);
            }
            if (ni == 0) {
                #pragma unroll
                for (int m = 0; m < 2; m++) scs[mi2 + m] = part[m];
            }
        }
        __syncwarp();

        // epilogue: coords + vel (lanes<8, one node each)
        if (lane < 8) {
            int nd = nbase + lane;
            if (nd < n) {
                float sc = scs[lane] + bv2s[0];
                #pragma unroll
                for (int q = 0; q < 3; q++) {
                    float4 sg = *(const float4*)(g_seg + nd*12 + q*4);
                    float4 Zv = *(const float4*)(Z + nd*12 + q*4);
                    float4 f  = make_float4(sg.x*icr, sg.y*icr, sg.z*icr, sg.w*icr);
                    *(float4*)(out_Z + nd*12 + q*4) =
                        make_float4(Zv.x+f.x, Zv.y+f.y, Zv.z+f.z, Zv.w+f.w);
                    if (q == 0) {
                        float v0 = sc * Z[nd*12 + 3] + f.x;
                        float v1 = sc * Z[nd*12 + 4] + f.y;
                        float v2 = sc * Z[nd*12 + 5] + f.z;
                        out_v[nd*3 + 0] = v0; out_v[nd*3 + 1] = v1; out_v[nd*3 + 2] = v2;
                        out_x[nd*3 + 0] = Zv.x + v0;
                        out_x[nd*3 + 1] = Zv.y + v1;
                        out_x[nd*3 + 2] = Zv.z + v2;
                    }
                }
            }
        }
        __syncwarp();
    }
}

// ---------------- launch ----------------
extern "C" void kernel_launch(void* const* d_in, const int* in_sizes, int n_in,
                              void* d_out, int out_size)
{
    const float* h   = (const float*)d_in[0];
    const float* Z   = (const float*)d_in[1];
    const int*   row = (const int*)  d_in[2];
    const int*   col = (const int*)  d_in[3];
    const float* We1 = (const float*)d_in[4];
    const float* be1 = (const float*)d_in[5];
    const float* We2 = (const float*)d_in[6];
    const float* be2 = (const float*)d_in[7];
    const float* Wn1 = (const float*)d_in[8];
    const float* bn1 = (const float*)d_in[9];
    const float* Wn2 = (const float*)d_in[10];
    const float* bn2 = (const float*)d_in[11];
    const float* Wc1 = (const float*)d_in[12];
    const float* bc1 = (const float*)d_in[13];
    const float* Wc2 = (const float*)d_in[14];
    const float* Wv1 = (const float*)d_in[15];
    const float* bv1 = (const float*)d_in[16];
    const float* Wv2 = (const float*)d_in[17];
    const float* bv2 = (const float*)d_in[18];

    const int n = in_sizes[0] / 64;
    const int E = in_sizes[2];

    float* out  = (float*)d_out;
    float* outh = out;
    float* outZ = out + (size_t)n * 64;
    float* outx = outZ + (size_t)n * 12;
    float* outv = outx + (size_t)n * 3;

    static int attr_done = 0;
    if (!attr_done) {
        cudaFuncSetAttribute(edge_kernel, cudaFuncAttributeMaxDynamicSharedMemorySize,
                             EDGE_SMEM_FLOATS * (int)sizeof(float));
        cudaFuncSetAttribute(node_kernel, cudaFuncAttributeMaxDynamicSharedMemorySize,
                             NODE_SMEM_FLOATS * (int)sizeof(float));
        attr_done = 1;
    }

    zero_scratch<<<1024, 256>>>(n);

    edge_kernel<<<148, 512, EDGE_SMEM_FLOATS * sizeof(float)>>>(
        h, Z, row, col, We1, be1, We2, be2, Wc1, bc1, Wc2, E);

    node_kernel<<<148, 512, NODE_SMEM_FLOATS * sizeof(float)>>>(
        h, Z, Wn1, bn1, Wn2, bn2, Wv1, bv1, Wv2, bv2,
        outh, outZ, outx, outv, n);
}

// round 9
// speedup vs baseline: 5.1137x; 1.8465x over previous
#include <cuda_runtime.h>
#include <cuda_bf16.h>
#include <math.h>
#include <stdint.h>

#define NNODES 50000
#define FIN    64
#define HID    64

typedef unsigned long long u64;

// ---------------- scratch (device globals; no allocation allowed) ----------------
__device__ float g_seg[NNODES * 12];
__device__ float g_agg[NNODES * 64];
__device__ float g_oth[NNODES * 64];
__device__ float g_cnt_row[NNODES];
__device__ float g_cnt_col[NNODES];

__global__ void zero_scratch(int n) {
    int tid = blockIdx.x * blockDim.x + threadIdx.x;
    int stride = gridDim.x * blockDim.x;
    for (int i = tid; i < n * 64; i += stride) { g_agg[i] = 0.f; g_oth[i] = 0.f; }
    for (int i = tid; i < n * 12; i += stride) g_seg[i] = 0.f;
    for (int i = tid; i < n; i += stride) { g_cnt_row[i] = 0.f; g_cnt_col[i] = 0.f; }
}

__device__ __forceinline__ void blk_copy(float* dst, const float* src, int n) {
    for (int i = threadIdx.x; i < n; i += blockDim.x) dst[i] = src[i];
}

// ---------------- helpers ----------------
__device__ __forceinline__ u64 pk2(float x, float y) {
    u64 r; asm("mov.b64 %0, {%1, %2};" : "=l"(r) : "f"(x), "f"(y)); return r;
}
__device__ __forceinline__ float2 upk2(u64 v) {
    float2 f; asm("mov.b64 {%0, %1}, %2;" : "=f"(f.x), "=f"(f.y) : "l"(v)); return f;
}
__device__ __forceinline__ u64 ffma2(u64 a, u64 b, u64 c) {
    u64 d; asm("fma.rn.f32x2 %0, %1, %2, %3;" : "=l"(d) : "l"(a), "l"(b), "l"(c)); return d;
}
__device__ __forceinline__ void red4(float* p, float a, float b, float c, float d) {
    asm volatile("red.global.add.v4.f32 [%0], {%1, %2, %3, %4};"
                 :: "l"(p), "f"(a), "f"(b), "f"(c), "f"(d) : "memory");
}
__device__ __forceinline__ void red2(float* p, float a, float b) {
    asm volatile("red.global.add.v2.f32 [%0], {%1, %2};"
                 :: "l"(p), "f"(a), "f"(b) : "memory");
}
__device__ __forceinline__ void red1(float* p, float a) {
    asm volatile("red.global.add.f32 [%0], %1;" :: "l"(p), "f"(a) : "memory");
}
__device__ __forceinline__ void cp16(void* dst_smem, const void* src) {
    unsigned d = (unsigned)__cvta_generic_to_shared(dst_smem);
    asm volatile("cp.async.ca.shared.global [%0], [%1], 16;" :: "r"(d), "l"(src));
}
__device__ __forceinline__ void cp_commit() { asm volatile("cp.async.commit_group;"); }
__device__ __forceinline__ void cp_wait0()  { asm volatile("cp.async.wait_group 0;" ::: "memory"); }

// round-to-nearest tf32 (19-bit) conversion; value stays in a float reg
__device__ __forceinline__ float tf32r(float x) {
    unsigned u;
    asm("cvt.rna.tf32.f32 %0, %1;" : "=r"(u) : "f"(x));
    return __uint_as_float(u);
}

// one m16n8k8 tf32 mma: D += A(16x8) * B(8x8)
__device__ __forceinline__ void mma8(float acc[4], float a0, float a1, float a2, float a3,
                                     float b0, float b1) {
    asm volatile(
        "mma.sync.aligned.m16n8k8.row.col.f32.tf32.tf32.f32 "
        "{%0,%1,%2,%3}, {%4,%5,%6,%7}, {%8,%9}, {%0,%1,%2,%3};"
        : "+f"(acc[0]), "+f"(acc[1]), "+f"(acc[2]), "+f"(acc[3])
        : "r"(__float_as_uint(a0)), "r"(__float_as_uint(a1)),
          "r"(__float_as_uint(a2)), "r"(__float_as_uint(a3)),
          "r"(__float_as_uint(b0)), "r"(__float_as_uint(b1)));
}

// Warp GEMM via tensor cores: [16 x NK] @ [NK x 64] + bias -> acc[8][4].
// A: smem, row-major, stride AS (tf32 values). WT: smem, N-major [64][WS] (tf32).
// Fragment ownership (g = lane>>2, t = lane&3):
//   acc[nb][0] = D[g][nb*8+2t]   acc[nb][1] = D[g][nb*8+2t+1]
//   acc[nb][2] = D[g+8][nb*8+2t] acc[nb][3] = D[g+8][nb*8+2t+1]
template<int NK, int AS, int WS>
__device__ __forceinline__ void wgemm_mma(const float* __restrict__ A,
                                          const float* __restrict__ WT,
                                          const float* __restrict__ bias,
                                          int g, int t, float acc[8][4])
{
    #pragma unroll
    for (int nb = 0; nb < 8; nb++) {
        float bx = bias[nb * 8 + 2 * t], by = bias[nb * 8 + 2 * t + 1];
        acc[nb][0] = bx; acc[nb][1] = by; acc[nb][2] = bx; acc[nb][3] = by;
    }
    #pragma unroll
    for (int ks = 0; ks < NK / 8; ks++) {
        const int kb = ks * 8;
        float a0 = A[g * AS + kb + t];
        float a1 = A[(g + 8) * AS + kb + t];
        float a2 = A[g * AS + kb + t + 4];
        float a3 = A[(g + 8) * AS + kb + t + 4];
        #pragma unroll
        for (int nb = 0; nb < 8; nb++) {
            float b0 = WT[(nb * 8 + g) * WS + kb + t];
            float b1 = WT[(nb * 8 + g) * WS + kb + t + 4];
            mma8(acc[nb], a0, a1, a2, a3, b0, b1);
        }
    }
}

// ---------------- edge kernel: 512 threads, 16 warps, 16-edge tile, tensor cores ----------------
#define EIN_STRIDE 148           // 148 % 32 == 20 -> conflict-free frag loads
#define WS1 148                  // We1T stride (needs >=144)
#define WS2 68                   // We2T/Wc1T stride (68 % 32 == 4)
#define OF_W1T 0                 // [64][148] = 9472
#define OF_W2T 9472              // [64][68]  = 4352
#define OF_W3T 13824             // [64][68]  = 4352
#define OF_B1  18176
#define OF_B2  18240
#define OF_B3  18304
#define OF_WC2 18368
#define OF_SCR 18432
#define EW_SCR (16*EIN_STRIDE + 32 + 16)   // eins + idxs + phis = 2416
#define EDGE_SMEM_FLOATS (OF_SCR + 16 * EW_SCR)   // 57088 floats = 228352 B

__global__ __launch_bounds__(512, 1)
void edge_kernel(const float* __restrict__ h, const float* __restrict__ Z,
                 const int* __restrict__ row, const int* __restrict__ col,
                 const float* __restrict__ We1, const float* __restrict__ be1,
                 const float* __restrict__ We2, const float* __restrict__ be2,
                 const float* __restrict__ Wc1, const float* __restrict__ bc1,
                 const float* __restrict__ Wc2,
                 int E)
{
    extern __shared__ float sm[];
    const int tid = threadIdx.x;

    // ---- stage weights transposed (N-major) with tf32 rounding ----
    for (int i = tid; i < 64 * 144; i += 512) {
        int n = i / 144, k = i % 144;
        sm[OF_W1T + n * WS1 + k] = tf32r(We1[k * 64 + n]);
    }
    for (int i = tid; i < 64 * 64; i += 512) {
        int n = i >> 6, k = i & 63;
        sm[OF_W2T + n * WS2 + k] = tf32r(We2[k * 64 + n]);
        sm[OF_W3T + n * WS2 + k] = tf32r(Wc1[k * 64 + n]);
    }
    blk_copy(sm + OF_B1, be1, 64);
    blk_copy(sm + OF_B2, be2, 64);
    blk_copy(sm + OF_B3, bc1, 64);
    blk_copy(sm + OF_WC2, Wc2, 64);
    __syncthreads();

    const int lane = tid & 31;
    const int warp = tid >> 5;
    float* eins = sm + OF_SCR + warp * EW_SCR;     // [16][148] tf32 data
    int*   idxs = (int*)(eins + 16 * EIN_STRIDE);  // [32]: 0..15 row, 16..31 col
    float* phis = (float*)(idxs + 32);             // [16]

    const int g = lane >> 2, t = lane & 3;
    const int sub = lane & 15;
    const bool is_col = lane >= 16;

    const int wg = blockIdx.x * 16 + warp;
    const int nw = gridDim.x * 16;
    const int ntiles = (E + 15) / 16;

    for (int tt = wg; tt < ntiles; tt += nw) {
        const int ebase = tt * 16;
        const int myedge = ebase + sub;

        // ---- phase A: indices ----
        int idxv = 0;
        if (myedge < E) idxv = is_col ? col[myedge] : row[myedge];
        idxs[lane] = idxv;
        __syncwarp();

        // ---- phase B: gather h[row] (cols 0..63), h[col] (cols 64..127), tf32 ----
        #pragma unroll 4
        for (int m = 0; m < 16; m++) {
            float2 vr = ((const float2*)(h + (size_t)idxs[m] * 64))[lane];
            vr.x = tf32r(vr.x); vr.y = tf32r(vr.y);
            *(float2*)(eins + m * EIN_STRIDE + 2 * lane) = vr;
            float2 vc = ((const float2*)(h + (size_t)idxs[16 + m] * 64))[lane];
            vc.x = tf32r(vc.x); vc.y = tf32r(vc.y);
            *(float2*)(eins + m * EIN_STRIDE + 64 + 2 * lane) = vc;
        }

        // ---- phase C: coord_diff + gram + radial -> cols 128..143 (lanes<16) ----
        float cd[12];
        if (lane < 16) {
            int r = idxs[lane], c = idxs[16 + lane];
            const float4* Zr = (const float4*)(Z + (size_t)r * 12);
            const float4* Zc = (const float4*)(Z + (size_t)c * 12);
            #pragma unroll
            for (int q = 0; q < 3; q++) {
                float4 a = Zr[q], b = Zc[q];
                cd[q*4+0] = a.x - b.x; cd[q*4+1] = a.y - b.y;
                cd[q*4+2] = a.z - b.z; cd[q*4+3] = a.w - b.w;
            }
            float gg[16]; float ss = 0.f;
            #pragma unroll
            for (int a = 0; a < 4; a++)
                #pragma unroll
                for (int b = 0; b < 4; b++) {
                    float v = cd[a*3]*cd[b*3] + cd[a*3+1]*cd[b*3+1] + cd[a*3+2]*cd[b*3+2];
                    gg[a*4+b] = v; ss += v * v;
                }
            float inv = 1.f / fmaxf(sqrtf(ss), 1e-12f);
            #pragma unroll
            for (int j = 0; j < 16; j++)
                eins[lane * EIN_STRIDE + 128 + j] = tf32r(gg[j] * inv);
        }
        if (myedge < E) red1(is_col ? &g_cnt_col[idxv] : &g_cnt_row[idxv], 1.f);
        __syncwarp();

        // ---- GEMM1 (tensor): [16x144]@[144x64] -> relu -> cols 64..127 ----
        {
            float acc[8][4];
            wgemm_mma<144, EIN_STRIDE, WS1>(eins, sm + OF_W1T, sm + OF_B1, g, t, acc);
            __syncwarp();  // all frag reads of cols 0..143 complete
            #pragma unroll
            for (int nb = 0; nb < 8; nb++) {
                float2 lo, hi;
                lo.x = tf32r(fmaxf(acc[nb][0], 0.f));
                lo.y = tf32r(fmaxf(acc[nb][1], 0.f));
                hi.x = tf32r(fmaxf(acc[nb][2], 0.f));
                hi.y = tf32r(fmaxf(acc[nb][3], 0.f));
                *(float2*)(eins + g * EIN_STRIDE + 64 + nb * 8 + 2 * t)       = lo;
                *(float2*)(eins + (g + 8) * EIN_STRIDE + 64 + nb * 8 + 2 * t) = hi;
            }
        }
        __syncwarp();

        // ---- GEMM2 (tensor): cols 64..127 @ We2T -> edge_feat; scatter + stage cols 0..63 ----
        {
            float acc2[8][4];
            wgemm_mma<64, EIN_STRIDE, WS2>(eins + 64, sm + OF_W2T, sm + OF_B2, g, t, acc2);
            const int rg = idxs[g],     cg = idxs[16 + g];
            const int rh = idxs[g + 8], ch = idxs[16 + g + 8];
            const bool okg = (ebase + g) < E, okh = (ebase + g + 8) < E;
            #pragma unroll
            for (int nb = 0; nb < 8; nb++) {
                float v0 = fmaxf(acc2[nb][0], 0.f), v1 = fmaxf(acc2[nb][1], 0.f);
                float v2 = fmaxf(acc2[nb][2], 0.f), v3 = fmaxf(acc2[nb][3], 0.f);
                float2 lo = make_float2(tf32r(v0), tf32r(v1));
                float2 hi = make_float2(tf32r(v2), tf32r(v3));
                *(float2*)(eins + g * EIN_STRIDE + nb * 8 + 2 * t)       = lo;
                *(float2*)(eins + (g + 8) * EIN_STRIDE + nb * 8 + 2 * t) = hi;
                const int cofs = nb * 8 + 2 * t;
                if (okg) {
                    red2(&g_agg[(size_t)rg * 64 + cofs], v0, v1);
                    red2(&g_oth[(size_t)cg * 64 + cofs], v0, v1);
                }
                if (okh) {
                    red2(&g_agg[(size_t)rh * 64 + cofs], v2, v3);
                    red2(&g_oth[(size_t)ch * 64 + cofs], v2, v3);
                }
            }
        }
        __syncwarp();

        // ---- GEMM3 (tensor): cols 0..63 @ Wc1T -> relu -> dot Wc2 -> phi ----
        {
            float acc3[8][4];
            wgemm_mma<64, EIN_STRIDE, WS2>(eins, sm + OF_W3T, sm + OF_B3, g, t, acc3);
            float p0 = 0.f, p1 = 0.f;
            #pragma unroll
            for (int nb = 0; nb < 8; nb++) {
                float w0 = sm[OF_WC2 + nb * 8 + 2 * t];
                float w1 = sm[OF_WC2 + nb * 8 + 2 * t + 1];
                p0 += fmaxf(acc3[nb][0], 0.f) * w0 + fmaxf(acc3[nb][1], 0.f) * w1;
                p1 += fmaxf(acc3[nb][2], 0.f) * w0 + fmaxf(acc3[nb][3], 0.f) * w1;
            }
            p0 += __shfl_xor_sync(0xffffffffu, p0, 1);
            p0 += __shfl_xor_sync(0xffffffffu, p0, 2);
            p1 += __shfl_xor_sync(0xffffffffu, p1, 1);
            p1 += __shfl_xor_sync(0xffffffffu, p1, 2);
            if (t == 0) { phis[g] = p0; phis[g + 8] = p1; }
        }
        __syncwarp();

        // ---- trans scatter: g_seg[row] += cd * phi (cd in registers) ----
        if (lane < 16 && myedge < E) {
            float ph = phis[lane];
            int r = idxs[lane];
            red4(&g_seg[(size_t)r * 12 + 0], cd[0]*ph, cd[1]*ph, cd[2]*ph,  cd[3]*ph);
            red4(&g_seg[(size_t)r * 12 + 4], cd[4]*ph, cd[5]*ph, cd[6]*ph,  cd[7]*ph);
            red4(&g_seg[(size_t)r * 12 + 8], cd[8]*ph, cd[9]*ph, cd[10]*ph, cd[11]*ph);
        }
        __syncwarp();
    }
}

// ---------------- node kernel: unchanged R4 FFMA path ----------------
template<int K, int AS, int MR>
__device__ __forceinline__ void wgemm(const float* __restrict__ A,
                                      const float* __restrict__ W,
                                      const float* __restrict__ bias,
                                      int mrow0, int ni8, u64 acc[MR][4])
{
    const u64* bp = (const u64*)(bias + ni8);
    u64 b0 = bp[0], b1 = bp[1], b2 = bp[2], b3 = bp[3];
    #pragma unroll
    for (int m = 0; m < MR; m++) { acc[m][0] = b0; acc[m][1] = b1; acc[m][2] = b2; acc[m][3] = b3; }

    #pragma unroll 2
    for (int k = 0; k < K; k++) {
        ulonglong2 wv0 = *(const ulonglong2*)(W + k * 64 + ni8);
        ulonglong2 wv1 = *(const ulonglong2*)(W + k * 64 + ni8 + 4);
        u64 w0 = wv0.x, w1 = wv0.y, w2 = wv1.x, w3 = wv1.y;
        #pragma unroll
        for (int m = 0; m < MR; m++) {
            float x = A[(mrow0 + m) * AS + k];
            u64 xp = pk2(x, x);
            acc[m][0] = ffma2(xp, w0, acc[m][0]);
            acc[m][1] = ffma2(xp, w1, acc[m][1]);
            acc[m][2] = ffma2(xp, w2, acc[m][2]);
            acc[m][3] = ffma2(xp, w3, acc[m][3]);
        }
    }
}

#define NIN_STRIDE 196
#define NW_SCR (8*NIN_STRIDE + 8 + 8)
#define NODE_SMEM_FLOATS (12288 + 4096 + 4096 + 64 + 64 + 64 + 64 + 16 + 16 * NW_SCR)

__global__ __launch_bounds__(512, 1)
void node_kernel(const float* __restrict__ h, const float* __restrict__ Z,
                 const float* __restrict__ Wn1, const float* __restrict__ bn1,
                 const float* __restrict__ Wn2, const float* __restrict__ bn2,
                 const float* __restrict__ Wv1, const float* __restrict__ bv1,
                 const float* __restrict__ Wv2, const float* __restrict__ bv2,
                 float* __restrict__ out_h, float* __restrict__ out_Z,
                 float* __restrict__ out_x, float* __restrict__ out_v,
                 int n)
{
    extern __shared__ float sm[];
    float* Wn1s = sm;
    float* Wn2s = Wn1s + 12288;
    float* Wv1s = Wn2s + 4096;
    float* Wv2s = Wv1s + 4096;
    float* bn1s = Wv2s + 64;
    float* bn2s = bn1s + 64;
    float* bv1s = bn2s + 64;
    float* bv2s = bv1s + 64;
    float* wscr = bv2s + 16;

    blk_copy(Wn1s, Wn1, 12288);
    blk_copy(Wn2s, Wn2, 4096);
    blk_copy(Wv1s, Wv1, 4096);
    blk_copy(Wv2s, Wv2, 64);
    blk_copy(bn1s, bn1, 64);
    blk_copy(bn2s, bn2, 64);
    blk_copy(bv1s, bv1, 64);
    if (threadIdx.x == 0) bv2s[0] = bv2[0];
    __syncthreads();

    const int lane = threadIdx.x & 31;
    const int warp = threadIdx.x >> 5;
    float* nins = wscr + warp * NW_SCR;
    float* iccs = nins + 8 * NIN_STRIDE;
    float* scs  = iccs + 8;

    const int mi = lane & 3, ni = lane >> 2;
    const int mi2 = mi * 2, ni8 = ni * 8;
    const int sub = lane & 15;
    const int half = lane >> 4;
    const unsigned FULL = 0xffffffffu;

    const int wg = blockIdx.x * 16 + warp;
    const int nw = gridDim.x * 16;
    const int ntiles = (n + 7) / 8;

    for (int t = wg; t < ntiles; t += nw) {
        const int nbase = t * 8;

        float icr = 1.f;
        if (lane < 8) {
            int nd = nbase + lane; if (nd >= n) nd = n - 1;
            icr = 1.f / fmaxf(g_cnt_row[nd], 1.f);
            iccs[lane] = 1.f / fmaxf(g_cnt_col[nd], 1.f);
        }

        #pragma unroll
        for (int mm = 0; mm < 4; mm++) {
            int m = 2 * mm + half;
            int nd = nbase + m; if (nd >= n) nd = n - 1;
            cp16(nins + m*NIN_STRIDE + sub*4,        g_oth + nd*64 + sub*4);
            cp16(nins + m*NIN_STRIDE + 64 + sub*4,  h     + nd*64 + sub*4);
            cp16(nins + m*NIN_STRIDE + 128 + sub*4, g_agg + nd*64 + sub*4);
        }
        cp_commit();
        cp_wait0();
        __syncwarp();

        {
            int m = lane >> 2;
            float icc = iccs[m];
            float4* p = (float4*)(nins + m*NIN_STRIDE + (lane & 3) * 16);
            #pragma unroll
            for (int q = 0; q < 4; q++) {
                float4 v = p[q];
                v.x *= icc; v.y *= icc; v.z *= icc; v.w *= icc;
                p[q] = v;
            }
        }
        __syncwarp();

        {
            u64 acc[2][4];
            wgemm<192, NIN_STRIDE, 2>(nins, Wn1s, bn1s, mi2, ni8, acc);
            __syncwarp();
            #pragma unroll
            for (int m = 0; m < 2; m++)
                #pragma unroll
                for (int p = 0; p < 4; p++) {
                    float2 v = upk2(acc[m][p]);
                    nins[(mi2+m)*NIN_STRIDE + ni8 + 2*p]     = fmaxf(v.x, 0.f);
                    nins[(mi2+m)*NIN_STRIDE + ni8 + 2*p + 1] = fmaxf(v.y, 0.f);
                }
        }
        __syncwarp();

        {
            u64 acc2[2][4];
            wgemm<64, NIN_STRIDE, 2>(nins, Wn2s, bn2s, mi2, ni8, acc2);
            #pragma unroll
            for (int m = 0; m < 2; m++) {
                int nd = nbase + mi2 + m;
                float4 h0 = *(float4*)(nins + (mi2+m)*NIN_STRIDE + 64 + ni8);
                float4 h1 = *(float4*)(nins + (mi2+m)*NIN_STRIDE + 64 + ni8 + 4);
                float2 v0 = upk2(acc2[m][0]), v1 = upk2(acc2[m][1]);
                float2 v2 = upk2(acc2[m][2]), v3 = upk2(acc2[m][3]);
                float4 hn0 = make_float4(h0.x + v0.x, h0.y + v0.y, h0.z + v1.x, h0.w + v1.y);
                float4 hn1 = make_float4(h1.x + v2.x, h1.y + v2.y, h1.z + v3.x, h1.w + v3.y);
                if (nd < n) {
                    *(float4*)(out_h + nd*64 + ni8)     = hn0;
                    *(float4*)(out_h + nd*64 + ni8 + 4) = hn1;
                }
                *(float4*)(nins + (mi2+m)*NIN_STRIDE + 128 + ni8)     = hn0;
                *(float4*)(nins + (mi2+m)*NIN_STRIDE + 128 + ni8 + 4) = hn1;
            }
        }
        __syncwarp();

        {
            u64 acc3[2][4];
            wgemm<64, NIN_STRIDE, 2>(nins + 128, Wv1s, bv1s, mi2, ni8, acc3);
            float2 wv[4];
            const u64* wp = (const u64*)(Wv2s + ni8);
            wv[0] = upk2(wp[0]); wv[1] = upk2(wp[1]); wv[2] = upk2(wp[2]); wv[3] = upk2(wp[3]);
            float prt[2];
            #pragma unroll
            for (int m = 0; m < 2; m++) {
                float s = 0.f;
                #pragma unroll
                for (int p = 0; p < 4; p++) {
                    float2 v = upk2(acc3[m][p]);
                    s += fmaxf(v.x, 0.f) * wv[p].x + fmaxf(v.y, 0.f) * wv[p].y;
                }
                prt[m] = s;
            }
            #pragma unroll
            for (int o = 4; o < 32; o <<= 1) {
                #pragma unroll
                for (int m = 0; m < 2; m++) prt[m] += __shfl_xor_sync(FULL, prt[m], o);
            }
            if (ni == 0) {
                #pragma unroll
                for (int m = 0; m < 2; m++) scs[mi2 + m] = prt[m];
            }
        }
        __syncwarp();

        if (lane < 8) {
            int nd = nbase + lane;
            if (nd < n) {
                float sc = scs[lane] + bv2s[0];
                #pragma unroll
                for (int q = 0; q < 3; q++) {
                    float4 sg = *(const float4*)(g_seg + nd*12 + q*4);
                    float4 Zv = *(const float4*)(Z + nd*12 + q*4);
                    float4 f  = make_float4(sg.x*icr, sg.y*icr, sg.z*icr, sg.w*icr);
                    *(float4*)(out_Z + nd*12 + q*4) =
                        make_float4(Zv.x+f.x, Zv.y+f.y, Zv.z+f.z, Zv.w+f.w);
                    if (q == 0) {
                        float v0 = sc * Z[nd*12 + 3] + f.x;
                        float v1 = sc * Z[nd*12 + 4] + f.y;
                        float v2 = sc * Z[nd*12 + 5] + f.z;
                        out_v[nd*3 + 0] = v0; out_v[nd*3 + 1] = v1; out_v[nd*3 + 2] = v2;
                        out_x[nd*3 + 0] = Zv.x + v0;
                        out_x[nd*3 + 1] = Zv.y + v1;
                        out_x[nd*3 + 2] = Zv.z + v2;
                    }
                }
            }
        }
        __syncwarp();
    }
}

// ---------------- launch ----------------
extern "C" void kernel_launch(void* const* d_in, const int* in_sizes, int n_in,
                              void* d_out, int out_size)
{
    const float* h   = (const float*)d_in[0];
    const float* Z   = (const float*)d_in[1];
    const int*   row = (const int*)  d_in[2];
    const int*   col = (const int*)  d_in[3];
    const float* We1 = (const float*)d_in[4];
    const float* be1 = (const float*)d_in[5];
    const float* We2 = (const float*)d_in[6];
    const float* be2 = (const float*)d_in[7];
    const float* Wn1 = (const float*)d_in[8];
    const float* bn1 = (const float*)d_in[9];
    const float* Wn2 = (const float*)d_in[10];
    const float* bn2 = (const float*)d_in[11];
    const float* Wc1 = (const float*)d_in[12];
    const float* bc1 = (const float*)d_in[13];
    const float* Wc2 = (const float*)d_in[14];
    const float* Wv1 = (const float*)d_in[15];
    const float* bv1 = (const float*)d_in[16];
    const float* Wv2 = (const float*)d_in[17];
    const float* bv2 = (const float*)d_in[18];

    const int n = in_sizes[0] / 64;
    const int E = in_sizes[2];

    float* out  = (float*)d_out;
    float* outh = out;
    float* outZ = out + (size_t)n * 64;
    float* outx = outZ + (size_t)n * 12;
    float* outv = outx + (size_t)n * 3;

    static int attr_done = 0;
    if (!attr_done) {
        cudaFuncSetAttribute(edge_kernel, cudaFuncAttributeMaxDynamicSharedMemorySize,
                             EDGE_SMEM_FLOATS * (int)sizeof(float));
        cudaFuncSetAttribute(node_kernel, cudaFuncAttributeMaxDynamicSharedMemorySize,
                             NODE_SMEM_FLOATS * (int)sizeof(float));
        attr_done = 1;
    }

    zero_scratch<<<1024, 256>>>(n);

    edge_kernel<<<148, 512, EDGE_SMEM_FLOATS * sizeof(float)>>>(
        h, Z, row, col, We1, be1, We2, be2, Wc1, bc1, Wc2, E);

    node_kernel<<<148, 512, NODE_SMEM_FLOATS * sizeof(float)>>>(
        h, Z, Wn1, bn1, Wn2, bn2, Wv1, bv1, Wv2, bv2,
        outh, outZ, outx, outv, n);
}

// round 10
// speedup vs baseline: 5.1901x; 1.0149x over previous
#include <cuda_runtime.h>
#include <cuda_bf16.h>
#include <math.h>
#include <stdint.h>

#define NNODES 50000
#define FIN    64
#define HID    64

typedef unsigned long long u64;

// ---------------- scratch (device globals; no allocation allowed) ----------------
__device__ float g_seg[NNODES * 12];
__device__ float g_agg[NNODES * 64];
__device__ float g_oth[NNODES * 64];
__device__ float g_cnt_row[NNODES];
__device__ float g_cnt_col[NNODES];

__global__ void zero_scratch(int n) {
    int tid = blockIdx.x * blockDim.x + threadIdx.x;
    int stride = gridDim.x * blockDim.x;
    for (int i = tid; i < n * 64; i += stride) { g_agg[i] = 0.f; g_oth[i] = 0.f; }
    for (int i = tid; i < n * 12; i += stride) g_seg[i] = 0.f;
    for (int i = tid; i < n; i += stride) { g_cnt_row[i] = 0.f; g_cnt_col[i] = 0.f; }
}

__device__ __forceinline__ void blk_copy(float* dst, const float* src, int n) {
    for (int i = threadIdx.x; i < n; i += blockDim.x) dst[i] = src[i];
}

// ---------------- helpers ----------------
__device__ __forceinline__ void red4(float* p, float a, float b, float c, float d) {
    asm volatile("red.global.add.v4.f32 [%0], {%1, %2, %3, %4};"
                 :: "l"(p), "f"(a), "f"(b), "f"(c), "f"(d) : "memory");
}
__device__ __forceinline__ void red1(float* p, float a) {
    asm volatile("red.global.add.f32 [%0], %1;" :: "l"(p), "f"(a) : "memory");
}

// round-to-nearest tf32 (19-bit); value stays in a float reg
__device__ __forceinline__ float tf32r(float x) {
    unsigned u;
    asm("cvt.rna.tf32.f32 %0, %1;" : "=r"(u) : "f"(x));
    return __uint_as_float(u);
}

// one m16n8k8 tf32 mma: D += A(16x8) * B(8x8)
__device__ __forceinline__ void mma8(float acc[4], float a0, float a1, float a2, float a3,
                                     float b0, float b1) {
    asm volatile(
        "mma.sync.aligned.m16n8k8.row.col.f32.tf32.tf32.f32 "
        "{%0,%1,%2,%3}, {%4,%5,%6,%7}, {%8,%9}, {%0,%1,%2,%3};"
        : "+f"(acc[0]), "+f"(acc[1]), "+f"(acc[2]), "+f"(acc[3])
        : "r"(__float_as_uint(a0)), "r"(__float_as_uint(a1)),
          "r"(__float_as_uint(a2)), "r"(__float_as_uint(a3)),
          "r"(__float_as_uint(b0)), "r"(__float_as_uint(b1)));
}

// Warp GEMM: [16 x NK] @ [NK x 64] + bias -> acc[8][4]. (full 64-N)
template<int NK, int AS, int WS>
__device__ __forceinline__ void wgemm_mma(const float* __restrict__ A,
                                          const float* __restrict__ WT,
                                          const float* __restrict__ bias,
                                          int g, int t, float acc[8][4])
{
    #pragma unroll
    for (int nb = 0; nb < 8; nb++) {
        float bx = bias[nb * 8 + 2 * t], by = bias[nb * 8 + 2 * t + 1];
        acc[nb][0] = bx; acc[nb][1] = by; acc[nb][2] = bx; acc[nb][3] = by;
    }
    #pragma unroll
    for (int ks = 0; ks < NK / 8; ks++) {
        const int kb = ks * 8;
        float a0 = A[g * AS + kb + t];
        float a1 = A[(g + 8) * AS + kb + t];
        float a2 = A[g * AS + kb + t + 4];
        float a3 = A[(g + 8) * AS + kb + t + 4];
        #pragma unroll
        for (int nb = 0; nb < 8; nb++) {
            float b0 = WT[(nb * 8 + g) * WS + kb + t];
            float b1 = WT[(nb * 8 + g) * WS + kb + t + 4];
            mma8(acc[nb], a0, a1, a2, a3, b0, b1);
        }
    }
}

// Half-N variant: [16 x NK] @ [NK x 32] + bias -> acc[4][4]. WT/bias pre-offset.
template<int NK, int AS, int WS>
__device__ __forceinline__ void wgemm_nb4(const float* __restrict__ A,
                                          const float* __restrict__ WT,
                                          const float* __restrict__ bias,
                                          int g, int t, float acc[4][4])
{
    #pragma unroll
    for (int nb = 0; nb < 4; nb++) {
        float bx = bias[nb * 8 + 2 * t], by = bias[nb * 8 + 2 * t + 1];
        acc[nb][0] = bx; acc[nb][1] = by; acc[nb][2] = bx; acc[nb][3] = by;
    }
    #pragma unroll
    for (int ks = 0; ks < NK / 8; ks++) {
        const int kb = ks * 8;
        float a0 = A[g * AS + kb + t];
        float a1 = A[(g + 8) * AS + kb + t];
        float a2 = A[g * AS + kb + t + 4];
        float a3 = A[(g + 8) * AS + kb + t + 4];
        #pragma unroll
        for (int nb = 0; nb < 4; nb++) {
            float b0 = WT[(nb * 8 + g) * WS + kb + t];
            float b1 = WT[(nb * 8 + g) * WS + kb + t + 4];
            mma8(acc[nb], a0, a1, a2, a3, b0, b1);
        }
    }
}

// ---------------- edge kernel: 512 threads, 16 warps, 16-edge tile, tensor cores ----------------
#define EIN_STRIDE 148
#define WS1 148
#define WS2 68
#define OF_W1T 0
#define OF_W2T 9472
#define OF_W3T 13824
#define OF_B1  18176
#define OF_B2  18240
#define OF_B3  18304
#define OF_WC2 18368
#define OF_SCR 18432
#define EW_SCR (16*EIN_STRIDE + 32 + 16)
#define EDGE_SMEM_FLOATS (OF_SCR + 16 * EW_SCR)

__global__ __launch_bounds__(512, 1)
void edge_kernel(const float* __restrict__ h, const float* __restrict__ Z,
                 const int* __restrict__ row, const int* __restrict__ col,
                 const float* __restrict__ We1, const float* __restrict__ be1,
                 const float* __restrict__ We2, const float* __restrict__ be2,
                 const float* __restrict__ Wc1, const float* __restrict__ bc1,
                 const float* __restrict__ Wc2,
                 int E)
{
    extern __shared__ float sm[];
    const int tid = threadIdx.x;

    for (int i = tid; i < 64 * 144; i += 512) {
        int n = i / 144, k = i % 144;
        sm[OF_W1T + n * WS1 + k] = tf32r(We1[k * 64 + n]);
    }
    for (int i = tid; i < 64 * 64; i += 512) {
        int n = i >> 6, k = i & 63;
        sm[OF_W2T + n * WS2 + k] = tf32r(We2[k * 64 + n]);
        sm[OF_W3T + n * WS2 + k] = tf32r(Wc1[k * 64 + n]);
    }
    blk_copy(sm + OF_B1, be1, 64);
    blk_copy(sm + OF_B2, be2, 64);
    blk_copy(sm + OF_B3, bc1, 64);
    blk_copy(sm + OF_WC2, Wc2, 64);
    __syncthreads();

    const int lane = tid & 31;
    const int warp = tid >> 5;
    float* eins = sm + OF_SCR + warp * EW_SCR;
    int*   idxs = (int*)(eins + 16 * EIN_STRIDE);
    float* phis = (float*)(idxs + 32);

    const int g = lane >> 2, t = lane & 3;
    const int sub = lane & 15;
    const bool is_col = lane >= 16;

    const int wg = blockIdx.x * 16 + warp;
    const int nw = gridDim.x * 16;
    const int ntiles = (E + 15) / 16;

    for (int tt = wg; tt < ntiles; tt += nw) {
        const int ebase = tt * 16;
        const int myedge = ebase + sub;

        // ---- phase A: indices ----
        int idxv = 0;
        if (myedge < E) idxv = is_col ? col[myedge] : row[myedge];
        idxs[lane] = idxv;
        __syncwarp();

        // ---- phase B: gather h[row]/h[col] (tf32) ----
        #pragma unroll 4
        for (int m = 0; m < 16; m++) {
            float2 vr = ((const float2*)(h + (size_t)idxs[m] * 64))[lane];
            vr.x = tf32r(vr.x); vr.y = tf32r(vr.y);
            *(float2*)(eins + m * EIN_STRIDE + 2 * lane) = vr;
            float2 vc = ((const float2*)(h + (size_t)idxs[16 + m] * 64))[lane];
            vc.x = tf32r(vc.x); vc.y = tf32r(vc.y);
            *(float2*)(eins + m * EIN_STRIDE + 64 + 2 * lane) = vc;
        }

        // ---- phase C: coord_diff + gram + radial -> cols 128..143 (lanes<16) ----
        float cd[12];
        if (lane < 16) {
            int r = idxs[lane], c = idxs[16 + lane];
            const float4* Zr = (const float4*)(Z + (size_t)r * 12);
            const float4* Zc = (const float4*)(Z + (size_t)c * 12);
            #pragma unroll
            for (int q = 0; q < 3; q++) {
                float4 a = Zr[q], b = Zc[q];
                cd[q*4+0] = a.x - b.x; cd[q*4+1] = a.y - b.y;
                cd[q*4+2] = a.z - b.z; cd[q*4+3] = a.w - b.w;
            }
            float gg[16]; float ss = 0.f;
            #pragma unroll
            for (int a = 0; a < 4; a++)
                #pragma unroll
                for (int b = 0; b < 4; b++) {
                    float v = cd[a*3]*cd[b*3] + cd[a*3+1]*cd[b*3+1] + cd[a*3+2]*cd[b*3+2];
                    gg[a*4+b] = v; ss += v * v;
                }
            float inv = 1.f / fmaxf(sqrtf(ss), 1e-12f);
            #pragma unroll
            for (int j = 0; j < 16; j++)
                eins[lane * EIN_STRIDE + 128 + j] = tf32r(gg[j] * inv);
        }
        if (myedge < E) red1(is_col ? &g_cnt_col[idxv] : &g_cnt_row[idxv], 1.f);
        __syncwarp();

        // ---- GEMM1: [16x144]@[144x64] -> relu -> cols 64..127 ----
        {
            float acc[8][4];
            wgemm_mma<144, EIN_STRIDE, WS1>(eins, sm + OF_W1T, sm + OF_B1, g, t, acc);
            __syncwarp();
            #pragma unroll
            for (int nb = 0; nb < 8; nb++) {
                float2 lo, hi;
                lo.x = tf32r(fmaxf(acc[nb][0], 0.f));
                lo.y = tf32r(fmaxf(acc[nb][1], 0.f));
                hi.x = tf32r(fmaxf(acc[nb][2], 0.f));
                hi.y = tf32r(fmaxf(acc[nb][3], 0.f));
                *(float2*)(eins + g * EIN_STRIDE + 64 + nb * 8 + 2 * t)       = lo;
                *(float2*)(eins + (g + 8) * EIN_STRIDE + 64 + nb * 8 + 2 * t) = hi;
            }
        }
        __syncwarp();

        // ---- GEMM2: cols 64..127 @ We2T -> edge_feat -> stage cols 0..63 ----
        {
            float acc2[8][4];
            wgemm_mma<64, EIN_STRIDE, WS2>(eins + 64, sm + OF_W2T, sm + OF_B2, g, t, acc2);
            #pragma unroll
            for (int nb = 0; nb < 8; nb++) {
                float2 lo, hi;
                lo.x = tf32r(fmaxf(acc2[nb][0], 0.f));
                lo.y = tf32r(fmaxf(acc2[nb][1], 0.f));
                hi.x = tf32r(fmaxf(acc2[nb][2], 0.f));
                hi.y = tf32r(fmaxf(acc2[nb][3], 0.f));
                *(float2*)(eins + g * EIN_STRIDE + nb * 8 + 2 * t)       = lo;
                *(float2*)(eins + (g + 8) * EIN_STRIDE + nb * 8 + 2 * t) = hi;
            }
        }
        __syncwarp();

        // ---- scatter agg/oth from staged smem: one lane per (edge, 32-col half) ----
        // red4 (16B lanes) instead of red2 (8B): half the REDG lane count.
        {
            const int m  = lane >> 1;
            const int co = (lane & 1) * 32;
            if (ebase + m < E) {
                const int r = idxs[m], c = idxs[16 + m];
                #pragma unroll
                for (int q = 0; q < 8; q++) {
                    int q2 = q ^ ((lane & 1) << 2);   // bank stagger
                    float4 v = *(float4*)(eins + m * EIN_STRIDE + co + q2 * 4);
                    red4(&g_agg[(size_t)r * 64 + co + q2 * 4], v.x, v.y, v.z, v.w);
                    red4(&g_oth[(size_t)c * 64 + co + q2 * 4], v.x, v.y, v.z, v.w);
                }
            }
        }

        // ---- GEMM3: cols 0..63 @ Wc1T -> relu -> dot Wc2 -> phi ----
        {
            float acc3[8][4];
            wgemm_mma<64, EIN_STRIDE, WS2>(eins, sm + OF_W3T, sm + OF_B3, g, t, acc3);
            float p0 = 0.f, p1 = 0.f;
            #pragma unroll
            for (int nb = 0; nb < 8; nb++) {
                float w0 = sm[OF_WC2 + nb * 8 + 2 * t];
                float w1 = sm[OF_WC2 + nb * 8 + 2 * t + 1];
                p0 += fmaxf(acc3[nb][0], 0.f) * w0 + fmaxf(acc3[nb][1], 0.f) * w1;
                p1 += fmaxf(acc3[nb][2], 0.f) * w0 + fmaxf(acc3[nb][3], 0.f) * w1;
            }
            p0 += __shfl_xor_sync(0xffffffffu, p0, 1);
            p0 += __shfl_xor_sync(0xffffffffu, p0, 2);
            p1 += __shfl_xor_sync(0xffffffffu, p1, 1);
            p1 += __shfl_xor_sync(0xffffffffu, p1, 2);
            if (t == 0) { phis[g] = p0; phis[g + 8] = p1; }
        }
        __syncwarp();

        // ---- trans scatter: g_seg[row] += cd * phi ----
        if (lane < 16 && myedge < E) {
            float ph = phis[lane];
            int r = idxs[lane];
            red4(&g_seg[(size_t)r * 12 + 0], cd[0]*ph, cd[1]*ph, cd[2]*ph,  cd[3]*ph);
            red4(&g_seg[(size_t)r * 12 + 4], cd[4]*ph, cd[5]*ph, cd[6]*ph,  cd[7]*ph);
            red4(&g_seg[(size_t)r * 12 + 8], cd[8]*ph, cd[9]*ph, cd[10]*ph, cd[11]*ph);
        }
        __syncwarp();
    }
}

// ---------------- node kernel: 512 threads, warp-pairs, tensor cores ----------------
#define NWS1 196
#define NWS2 68
#define N_OF_W1T 0          // Wn1T [64][196] = 12544
#define N_OF_W2T 12544      // Wn2T [64][68]  = 4352
#define N_OF_W3T 16896      // Wv1T [64][68]  = 4352
#define N_OF_B1  21248
#define N_OF_B2  21312
#define N_OF_BV1 21376
#define N_OF_WV2 21440
#define N_OF_BV2 21504      // 16
#define N_OF_SCR 21520
#define NP_SCR (16*NWS1 + 16 + 16 + 32)   // nins + iccs + icrs + scs = 3200
#define NODE_SMEM_FLOATS (N_OF_SCR + 8 * NP_SCR)   // 47120 floats = 188480 B

__global__ __launch_bounds__(512, 1)
void node_kernel(const float* __restrict__ h, const float* __restrict__ Z,
                 const float* __restrict__ Wn1, const float* __restrict__ bn1,
                 const float* __restrict__ Wn2, const float* __restrict__ bn2,
                 const float* __restrict__ Wv1, const float* __restrict__ bv1,
                 const float* __restrict__ Wv2, const float* __restrict__ bv2,
                 float* __restrict__ out_h, float* __restrict__ out_Z,
                 float* __restrict__ out_x, float* __restrict__ out_v,
                 int n)
{
    extern __shared__ float sm[];
    const int tid = threadIdx.x;

    for (int i = tid; i < 64 * 192; i += 512) {
        int nn = i / 192, k = i % 192;
        sm[N_OF_W1T + nn * NWS1 + k] = tf32r(Wn1[k * 64 + nn]);
    }
    for (int i = tid; i < 64 * 64; i += 512) {
        int nn = i >> 6, k = i & 63;
        sm[N_OF_W2T + nn * NWS2 + k] = tf32r(Wn2[k * 64 + nn]);
        sm[N_OF_W3T + nn * NWS2 + k] = tf32r(Wv1[k * 64 + nn]);
    }
    blk_copy(sm + N_OF_B1, bn1, 64);
    blk_copy(sm + N_OF_B2, bn2, 64);
    blk_copy(sm + N_OF_BV1, bv1, 64);
    blk_copy(sm + N_OF_WV2, Wv2, 64);
    if (tid == 0) sm[N_OF_BV2] = bv2[0];
    __syncthreads();

    const int lane = tid & 31;
    const int warp = tid >> 5;
    const int pair = warp >> 1;
    const int half = warp & 1;
    float* nins = sm + N_OF_SCR + pair * NP_SCR;   // [16][196]
    float* iccs = nins + 16 * NWS1;                // [16]
    float* icrs = iccs + 16;                       // [16]
    float* scs  = icrs + 16;                       // [32]: node*2 + half

    const int g = lane >> 2, t = lane & 3;
    const int ncol0 = half * 32;

    const int ntiles = (n + 127) / 128;

    for (int bt = blockIdx.x; bt < ntiles; bt += gridDim.x) {
        const int nbase = bt * 128 + pair * 16;

        if (half == 0 && lane < 16) {
            int nd = nbase + lane; if (nd >= n) nd = n - 1;
            icrs[lane] = 1.f / fmaxf(g_cnt_row[nd], 1.f);
            iccs[lane] = 1.f / fmaxf(g_cnt_col[nd], 1.f);
        }
        __syncthreads();

        // ---- gather + tf32 convert: warp covers rows half*8..+7, 48 chunks each ----
        #pragma unroll
        for (int j = 0; j < 12; j++) {
            int idx = lane + 32 * j;       // 0..383
            int rr = idx / 48, ch = idx % 48;
            int rowi = half * 8 + rr;
            int nd = nbase + rowi; if (nd >= n) nd = n - 1;
            const float* src;
            float mul = 1.f;
            if (ch < 16)      { src = g_oth + (size_t)nd * 64 + ch * 4; mul = iccs[rowi]; }
            else if (ch < 32) { src = h     + (size_t)nd * 64 + (ch - 16) * 4; }
            else              { src = g_agg + (size_t)nd * 64 + (ch - 32) * 4; }
            float4 v = *(const float4*)src;
            v.x = tf32r(v.x * mul); v.y = tf32r(v.y * mul);
            v.z = tf32r(v.z * mul); v.w = tf32r(v.w * mul);
            *(float4*)(nins + rowi * NWS1 + ch * 4) = v;
        }
        __syncthreads();

        // ---- GEMM1: [16x192]@[192x32(own)] -> relu -> act1 cols 0..63 ----
        {
            float acc[4][4];
            wgemm_nb4<192, NWS1, NWS1>(nins, sm + N_OF_W1T + ncol0 * NWS1,
                                       sm + N_OF_B1 + ncol0, g, t, acc);
            __syncthreads();   // all pairs' frag reads of cols 0..191 done
            #pragma unroll
            for (int nb = 0; nb < 4; nb++) {
                int colc = ncol0 + nb * 8 + 2 * t;
                float2 lo, hi;
                lo.x = tf32r(fmaxf(acc[nb][0], 0.f));
                lo.y = tf32r(fmaxf(acc[nb][1], 0.f));
                hi.x = tf32r(fmaxf(acc[nb][2], 0.f));
                hi.y = tf32r(fmaxf(acc[nb][3], 0.f));
                *(float2*)(nins + g * NWS1 + colc)       = lo;
                *(float2*)(nins + (g + 8) * NWS1 + colc) = hi;
            }
        }
        __syncthreads();

        // ---- GEMM2: cols 0..63 @ Wn2T -> + h residual -> out_h; stage tf32 -> cols 64..127 ----
        {
            float acc2[4][4];
            wgemm_nb4<64, NWS1, NWS2>(nins, sm + N_OF_W2T + ncol0 * NWS2,
                                      sm + N_OF_B2 + ncol0, g, t, acc2);
            int nd_lo = nbase + g, nd_hi = nbase + g + 8;
            int cl_lo = nd_lo < n ? nd_lo : n - 1;
            int cl_hi = nd_hi < n ? nd_hi : n - 1;
            #pragma unroll
            for (int nb = 0; nb < 4; nb++) {
                int colc = ncol0 + nb * 8 + 2 * t;
                float2 hr_lo = *(const float2*)(h + (size_t)cl_lo * 64 + colc);
                float2 hr_hi = *(const float2*)(h + (size_t)cl_hi * 64 + colc);
                float2 hn_lo = make_float2(hr_lo.x + acc2[nb][0], hr_lo.y + acc2[nb][1]);
                float2 hn_hi = make_float2(hr_hi.x + acc2[nb][2], hr_hi.y + acc2[nb][3]);
                if (nd_lo < n) *(float2*)(out_h + (size_t)nd_lo * 64 + colc) = hn_lo;
                if (nd_hi < n) *(float2*)(out_h + (size_t)nd_hi * 64 + colc) = hn_hi;
                float2 s_lo = make_float2(tf32r(hn_lo.x), tf32r(hn_lo.y));
                float2 s_hi = make_float2(tf32r(hn_hi.x), tf32r(hn_hi.y));
                *(float2*)(nins + g * NWS1 + 64 + colc)       = s_lo;
                *(float2*)(nins + (g + 8) * NWS1 + 64 + colc) = s_hi;
            }
        }
        __syncthreads();

        // ---- GEMM3 (vel): cols 64..127 @ Wv1T -> relu . Wv2 -> scale partials ----
        {
            float acc3[4][4];
            wgemm_nb4<64, NWS1, NWS2>(nins + 64, sm + N_OF_W3T + ncol0 * NWS2,
                                      sm + N_OF_BV1 + ncol0, g, t, acc3);
            float p0 = 0.f, p1 = 0.f;
            #pragma unroll
            for (int nb = 0; nb < 4; nb++) {
                float w0 = sm[N_OF_WV2 + ncol0 + nb * 8 + 2 * t];
                float w1 = sm[N_OF_WV2 + ncol0 + nb * 8 + 2 * t + 1];
                p0 += fmaxf(acc3[nb][0], 0.f) * w0 + fmaxf(acc3[nb][1], 0.f) * w1;
                p1 += fmaxf(acc3[nb][2], 0.f) * w0 + fmaxf(acc3[nb][3], 0.f) * w1;
            }
            p0 += __shfl_xor_sync(0xffffffffu, p0, 1);
            p0 += __shfl_xor_sync(0xffffffffu, p0, 2);
            p1 += __shfl_xor_sync(0xffffffffu, p1, 1);
            p1 += __shfl_xor_sync(0xffffffffu, p1, 2);
            if (t == 0) { scs[g * 2 + half] = p0; scs[(g + 8) * 2 + half] = p1; }
        }
        __syncthreads();

        // ---- epilogue: coords + vel (half==0 warp, lanes<16) ----
        if (half == 0 && lane < 16) {
            int nd = nbase + lane;
            if (nd < n) {
                float sc = scs[lane * 2] + scs[lane * 2 + 1] + sm[N_OF_BV2];
                float icr = icrs[lane];
                #pragma unroll
                for (int q = 0; q < 3; q++) {
                    float4 sg = *(const float4*)(g_seg + (size_t)nd * 12 + q * 4);
                    float4 Zv = *(const float4*)(Z + (size_t)nd * 12 + q * 4);
                    float4 f  = make_float4(sg.x*icr, sg.y*icr, sg.z*icr, sg.w*icr);
                    *(float4*)(out_Z + (size_t)nd * 12 + q * 4) =
                        make_float4(Zv.x+f.x, Zv.y+f.y, Zv.z+f.z, Zv.w+f.w);
                    if (q == 0) {
                        float v0 = sc * Z[nd*12 + 3] + f.x;
                        float v1 = sc * Z[nd*12 + 4] + f.y;
                        float v2 = sc * Z[nd*12 + 5] + f.z;
                        out_v[nd*3 + 0] = v0; out_v[nd*3 + 1] = v1; out_v[nd*3 + 2] = v2;
                        out_x[nd*3 + 0] = Zv.x + v0;
                        out_x[nd*3 + 1] = Zv.y + v1;
                        out_x[nd*3 + 2] = Zv.z + v2;
                    }
                }
            }
        }
        __syncthreads();   // protect nins/scs reuse next iteration
    }
}

// ---------------- launch ----------------
extern "C" void kernel_launch(void* const* d_in, const int* in_sizes, int n_in,
                              void* d_out, int out_size)
{
    const float* h   = (const float*)d_in[0];
    const float* Z   = (const float*)d_in[1];
    const int*   row = (const int*)  d_in[2];
    const int*   col = (const int*)  d_in[3];
    const float* We1 = (const float*)d_in[4];
    const float* be1 = (const float*)d_in[5];
    const float* We2 = (const float*)d_in[6];
    const float* be2 = (const float*)d_in[7];
    const float* Wn1 = (const float*)d_in[8];
    const float* bn1 = (const float*)d_in[9];
    const float* Wn2 = (const float*)d_in[10];
    const float* bn2 = (const float*)d_in[11];
    const float* Wc1 = (const float*)d_in[12];
    const float* bc1 = (const float*)d_in[13];
    const float* Wc2 = (const float*)d_in[14];
    const float* Wv1 = (const float*)d_in[15];
    const float* bv1 = (const float*)d_in[16];
    const float* Wv2 = (const float*)d_in[17];
    const float* bv2 = (const float*)d_in[18];

    const int n = in_sizes[0] / 64;
    const int E = in_sizes[2];

    float* out  = (float*)d_out;
    float* outh = out;
    float* outZ = out + (size_t)n * 64;
    float* outx = outZ + (size_t)n * 12;
    float* outv = outx + (size_t)n * 3;

    static int attr_done = 0;
    if (!attr_done) {
        cudaFuncSetAttribute(edge_kernel, cudaFuncAttributeMaxDynamicSharedMemorySize,
                             EDGE_SMEM_FLOATS * (int)sizeof(float));
        cudaFuncSetAttribute(node_kernel, cudaFuncAttributeMaxDynamicSharedMemorySize,
                             NODE_SMEM_FLOATS * (int)sizeof(float));
        attr_done = 1;
    }

    zero_scratch<<<1024, 256>>>(n);

    edge_kernel<<<148, 512, EDGE_SMEM_FLOATS * sizeof(float)>>>(
        h, Z, row, col, We1, be1, We2, be2, Wc1, bc1, Wc2, E);

    node_kernel<<<148, 512, NODE_SMEM_FLOATS * sizeof(float)>>>(
        h, Z, Wn1, bn1, Wn2, bn2, Wv1, bv1, Wv2, bv2,
        outh, outZ, outx, outv, n);
}